// round 2
// baseline (speedup 1.0000x reference)
#include <cuda_runtime.h>

// Problem dims (fixed by the dataset)
#define TT 256
#define BB 1024
#define NROW (TT*BB)   // 262144

typedef unsigned long long u64;

// -------- device scratch (no allocations allowed) --------
__device__ float g_hid[(size_t)NROW * 128];   // encoder output        134MB
__device__ float g_xg [(size_t)NROW * 512];   // x@Wih.T + bih + bhh   537MB
__device__ float g_hs [(size_t)NROW * 128];   // LSTM hidden states    134MB
__device__ float g_w1t [128 * 128];           // W1 transposed [k][o]
__device__ float g_w2t [128 * 32];
__device__ float g_w3t [32 * 128];
__device__ float g_wihT[128 * 512];
__device__ float g_whhT[128 * 512];
__device__ float g_whead[19 * 128];           // [Wa;Wc]
__device__ float g_bhead[19];
__device__ float g_biasg[512];                // bih + bhh

// -------- packed f32x2 helpers --------
__device__ __forceinline__ u64 pk2(float lo, float hi) {
    u64 r; asm("mov.b64 %0,{%1,%2};" : "=l"(r) : "f"(lo), "f"(hi)); return r;
}
__device__ __forceinline__ u64 dup2(float v) { return pk2(v, v); }
__device__ __forceinline__ void upk(u64 p, float& lo, float& hi) {
    asm("mov.b64 {%0,%1},%2;" : "=f"(lo), "=f"(hi) : "l"(p));
}
__device__ __forceinline__ u64 ffma2(u64 a, u64 b, u64 c) {
    u64 d; asm("fma.rn.f32x2 %0,%1,%2,%3;" : "=l"(d) : "l"(a), "l"(b), "l"(c)); return d;
}
__device__ __forceinline__ u64 fmul2(u64 a, u64 b) {
    u64 d; asm("mul.rn.f32x2 %0,%1,%2;" : "=l"(d) : "l"(a), "l"(b)); return d;
}
__device__ __forceinline__ float sig_f(float v) {
    return __fdividef(1.f, 1.f + __expf(-v));
}
__device__ __forceinline__ float tanh_f(float v) {
    return 2.f * sig_f(2.f * v) - 1.f;
}

// -------- prep: transpose weights, fold biases --------
__global__ void k_prep(const float* __restrict__ W1, const float* __restrict__ W2,
                       const float* __restrict__ W3, const float* __restrict__ Wih,
                       const float* __restrict__ Whh, const float* __restrict__ Wa,
                       const float* __restrict__ ba, const float* __restrict__ Wc,
                       const float* __restrict__ bc, const float* __restrict__ bih,
                       const float* __restrict__ bhh)
{
    int i0 = blockIdx.x * blockDim.x + threadIdx.x;
    int stride = gridDim.x * blockDim.x;
    for (int i = i0; i < 128*128; i += stride) { int k = i >> 7, o = i & 127; g_w1t[i] = W1[o*128 + k]; }
    for (int i = i0; i < 128*32;  i += stride) { int k = i / 32, o = i % 32;  g_w2t[i] = W2[o*128 + k]; }
    for (int i = i0; i < 32*128;  i += stride) { int k = i >> 7, o = i & 127; g_w3t[i] = W3[o*32  + k]; }
    for (int i = i0; i < 128*512; i += stride) { int k = i >> 9, o = i & 511; g_wihT[i] = Wih[o*128 + k]; }
    for (int i = i0; i < 128*512; i += stride) { int k = i >> 9, o = i & 511; g_whhT[i] = Whh[o*128 + k]; }
    for (int i = i0; i < 19*128;  i += stride) { int o = i >> 7, k = i & 127; g_whead[i] = (o < 18) ? Wa[o*128 + k] : Wc[k]; }
    for (int i = i0; i < 19;      i += stride) g_bhead[i] = (i < 18) ? ba[i] : bc[0];
    for (int i = i0; i < 512;     i += stride) g_biasg[i] = bih[i] + bhh[i];
}

// -------- fused 3-layer MLP encoder: 16 rows/block --------
__global__ void __launch_bounds__(256) k_enc(const float* __restrict__ x,
    const float* __restrict__ b1, const float* __restrict__ b2, const float* __restrict__ b3)
{
    __shared__ float xs [16][132];
    __shared__ float h1s[16][132];
    __shared__ float h2s[16][36];
    int tid = threadIdx.x;
    size_t row0 = (size_t)blockIdx.x * 16;
    for (int i = tid; i < 16*128; i += 256) { int r = i >> 7, k = i & 127; xs[r][k] = x[(row0 + r)*128 + k]; }
    __syncthreads();
    int tx = tid & 15, ty = tid >> 4;
    int c0 = tx * 8;
    // stage 1: relu(x @ W1T + b1) -> h1s [16][128]
    {
        u64 acc[4];
        ulonglong2 bb0 = *(const ulonglong2*)&b1[c0];
        ulonglong2 bb1 = *(const ulonglong2*)&b1[c0 + 4];
        acc[0] = bb0.x; acc[1] = bb0.y; acc[2] = bb1.x; acc[3] = bb1.y;
        #pragma unroll 8
        for (int k = 0; k < 128; k++) {
            ulonglong2 w0 = *(const ulonglong2*)&g_w1t[k*128 + c0];
            ulonglong2 w1 = *(const ulonglong2*)&g_w1t[k*128 + c0 + 4];
            u64 A = dup2(xs[ty][k]);
            acc[0] = ffma2(A, w0.x, acc[0]); acc[1] = ffma2(A, w0.y, acc[1]);
            acc[2] = ffma2(A, w1.x, acc[2]); acc[3] = ffma2(A, w1.y, acc[3]);
        }
        #pragma unroll
        for (int cp = 0; cp < 4; cp++) {
            float lo, hi; upk(acc[cp], lo, hi);
            h1s[ty][c0 + 2*cp]     = fmaxf(lo, 0.f);
            h1s[ty][c0 + 2*cp + 1] = fmaxf(hi, 0.f);
        }
    }
    __syncthreads();
    // stage 2: relu(h1 @ W2T + b2) -> h2s [16][32]
    {
        int r = tid >> 4;          // 0..15
        int c = (tid & 15) * 2;    // 0..30
        u64 acc = *(const u64*)&b2[c];
        #pragma unroll 8
        for (int k = 0; k < 128; k++) {
            u64 w = *(const u64*)&g_w2t[k*32 + c];
            u64 A = dup2(h1s[r][k]);
            acc = ffma2(A, w, acc);
        }
        float lo, hi; upk(acc, lo, hi);
        h2s[r][c] = fmaxf(lo, 0.f); h2s[r][c + 1] = fmaxf(hi, 0.f);
    }
    __syncthreads();
    // stage 3: relu(h2 @ W3T + b3) -> g_hid [16][128]
    {
        u64 acc[4];
        ulonglong2 bb0 = *(const ulonglong2*)&b3[c0];
        ulonglong2 bb1 = *(const ulonglong2*)&b3[c0 + 4];
        acc[0] = bb0.x; acc[1] = bb0.y; acc[2] = bb1.x; acc[3] = bb1.y;
        #pragma unroll
        for (int k = 0; k < 32; k++) {
            ulonglong2 w0 = *(const ulonglong2*)&g_w3t[k*128 + c0];
            ulonglong2 w1 = *(const ulonglong2*)&g_w3t[k*128 + c0 + 4];
            u64 A = dup2(h2s[ty][k]);
            acc[0] = ffma2(A, w0.x, acc[0]); acc[1] = ffma2(A, w0.y, acc[1]);
            acc[2] = ffma2(A, w1.x, acc[2]); acc[3] = ffma2(A, w1.y, acc[3]);
        }
        float* dst = &g_hid[(row0 + ty)*128 + c0];
        #pragma unroll
        for (int cp = 0; cp < 4; cp++) {
            float lo, hi; upk(acc[cp], lo, hi);
            *(float2*)&dst[2*cp] = make_float2(fmaxf(lo, 0.f), fmaxf(hi, 0.f));
        }
    }
}

// -------- xg = hid @ WihT + (bih+bhh): 64 rows x 128 cols per block --------
__global__ void __launch_bounds__(256) k_xg()
{
    __shared__ float As[64][132];
    int tid = threadIdx.x;
    size_t row0 = (size_t)blockIdx.x * 64;
    int cb = blockIdx.y * 128;
    for (int i = tid; i < 64*128; i += 256) { int r = i >> 7, k = i & 127; As[r][k] = g_hid[(row0 + r)*128 + k]; }
    __syncthreads();
    int tx = tid & 15, ty = tid >> 4;
    int c0 = cb + tx * 8;
    u64 acc[4][4];
    {
        ulonglong2 bb0 = *(const ulonglong2*)&g_biasg[c0];
        ulonglong2 bb1 = *(const ulonglong2*)&g_biasg[c0 + 4];
        #pragma unroll
        for (int i = 0; i < 4; i++) { acc[i][0] = bb0.x; acc[i][1] = bb0.y; acc[i][2] = bb1.x; acc[i][3] = bb1.y; }
    }
    #pragma unroll 4
    for (int k = 0; k < 128; k++) {
        ulonglong2 w0 = *(const ulonglong2*)&g_wihT[k*512 + c0];
        ulonglong2 w1 = *(const ulonglong2*)&g_wihT[k*512 + c0 + 4];
        #pragma unroll
        for (int i = 0; i < 4; i++) {
            u64 A = dup2(As[ty*4 + i][k]);
            acc[i][0] = ffma2(A, w0.x, acc[i][0]); acc[i][1] = ffma2(A, w0.y, acc[i][1]);
            acc[i][2] = ffma2(A, w1.x, acc[i][2]); acc[i][3] = ffma2(A, w1.y, acc[i][3]);
        }
    }
    #pragma unroll
    for (int i = 0; i < 4; i++) {
        float* dst = &g_xg[(row0 + ty*4 + i)*512 + c0];
        #pragma unroll
        for (int cp = 0; cp < 4; cp++) {
            float lo, hi; upk(acc[i][cp], lo, hi);
            *(float2*)&dst[2*cp] = make_float2(lo, hi);
        }
    }
}

// -------- LSTM recurrence: 8 batch elems/block (4 packed pairs), 128 blocks --------
// thread j (0..511) owns gate j for all 8 elements; c lives in regs of threads 0..127.
__global__ void __launch_bounds__(512) k_rec(const float* __restrict__ done,
    const float* __restrict__ h0, const float* __restrict__ c0)
{
    __shared__ __align__(16) float2 hsm[128][4];   // h, packed pairs
    __shared__ __align__(16) float2 act[512][4];   // activated gates
    __shared__ float dmask[8];
    int j = threadIdx.x;
    int base = blockIdx.x * 8;
    u64 c2[4];
    if (j < 128) {
        #pragma unroll
        for (int p = 0; p < 4; p++) {
            int b0 = base + 2*p;
            hsm[j][p] = make_float2(h0[b0*128 + j], h0[(b0 + 1)*128 + j]);
            c2[p] = pk2(c0[b0*128 + j], c0[(b0 + 1)*128 + j]);
        }
    }
    for (int t = 0; t < TT; t++) {
        if (j < 8) dmask[j] = 1.0f - done[t*BB + base + j];
        __syncthreads();
        if (j < 128) {  // reset mask applies to incoming h,c
            #pragma unroll
            for (int p = 0; p < 4; p++) {
                float m0 = dmask[2*p], m1 = dmask[2*p + 1];
                c2[p] = fmul2(c2[p], pk2(m0, m1));
                float2 h = hsm[j][p];
                h.x *= m0; h.y *= m1;
                hsm[j][p] = h;
            }
        }
        __syncthreads();
        // gates = xg[t] + h @ WhhT
        u64 acc[4];
        {
            const float* xr = g_xg + (size_t)(t*BB + base)*512 + j;
            #pragma unroll
            for (int p = 0; p < 4; p++) acc[p] = pk2(xr[(2*p)*512], xr[(2*p + 1)*512]);
        }
        #pragma unroll 8
        for (int k = 0; k < 128; k++) {
            u64 W = dup2(g_whhT[k*512 + j]);
            ulonglong2 h01 = *(const ulonglong2*)&hsm[k][0];
            ulonglong2 h23 = *(const ulonglong2*)&hsm[k][2];
            acc[0] = ffma2(W, h01.x, acc[0]); acc[1] = ffma2(W, h01.y, acc[1]);
            acc[2] = ffma2(W, h23.x, acc[2]); acc[3] = ffma2(W, h23.y, acc[3]);
        }
        bool is_g = (j >= 256) && (j < 384);   // tanh gate
        #pragma unroll
        for (int p = 0; p < 4; p++) {
            float lo, hi; upk(acc[p], lo, hi);
            if (is_g) { lo = tanh_f(lo); hi = tanh_f(hi); }
            else      { lo = sig_f(lo);  hi = sig_f(hi);  }
            act[j][p] = make_float2(lo, hi);
        }
        __syncthreads();
        if (j < 128) {  // cell update for cell j, all 8 elems
            #pragma unroll
            for (int p = 0; p < 4; p++) {
                u64 iv = *(const u64*)&act[j      ][p];
                u64 fv = *(const u64*)&act[j + 128][p];
                u64 gv = *(const u64*)&act[j + 256][p];
                u64 ov = *(const u64*)&act[j + 384][p];
                c2[p] = ffma2(fv, c2[p], fmul2(iv, gv));
                float cl, ch; upk(c2[p], cl, ch);
                float ol, oh; upk(ov, ol, oh);
                float hl = ol * tanh_f(cl);
                float hh = oh * tanh_f(ch);
                hsm[j][p] = make_float2(hl, hh);
                size_t r0 = ((size_t)t*BB + base + 2*p)*128 + j;
                g_hs[r0]       = hl;
                g_hs[r0 + 128] = hh;
            }
        }
        __syncthreads();
    }
}

// -------- heads: out[r][0:18]=hs@WaT+ba, out[r][18]=hs@WcT+bc --------
__global__ void __launch_bounds__(256) k_head(float* __restrict__ out)
{
    __shared__ float hsx[64][132];
    __shared__ float wh[19][132];
    __shared__ float bh[19];
    int tid = threadIdx.x;
    size_t row0 = (size_t)blockIdx.x * 64;
    for (int i = tid; i < 64*128; i += 256) { int r = i >> 7, k = i & 127; hsx[r][k] = g_hs[(row0 + r)*128 + k]; }
    for (int i = tid; i < 19*128; i += 256) { int o = i >> 7, k = i & 127; wh[o][k] = g_whead[i]; }
    if (tid < 19) bh[tid] = g_bhead[tid];
    __syncthreads();
    for (int oi = tid; oi < 64*19; oi += 256) {
        int r = oi / 19, c = oi - r*19;
        float acc = bh[c];
        #pragma unroll
        for (int k = 0; k < 128; k += 4) {
            float4 a = *(const float4*)&hsx[r][k];
            float4 w = *(const float4*)&wh[c][k];
            acc += a.x*w.x + a.y*w.y + a.z*w.z + a.w*w.w;
        }
        out[(row0 + r)*19 + c] = acc;
    }
}

extern "C" void kernel_launch(void* const* d_in, const int* in_sizes, int n_in,
                              void* d_out, int out_size)
{
    const float* x    = (const float*)d_in[0];
    const float* done = (const float*)d_in[1];
    const float* h0   = (const float*)d_in[2];
    const float* c0   = (const float*)d_in[3];
    const float* W1   = (const float*)d_in[4];
    const float* b1   = (const float*)d_in[5];
    const float* W2   = (const float*)d_in[6];
    const float* b2   = (const float*)d_in[7];
    const float* W3   = (const float*)d_in[8];
    const float* b3   = (const float*)d_in[9];
    const float* Wih  = (const float*)d_in[10];
    const float* Whh  = (const float*)d_in[11];
    const float* bih  = (const float*)d_in[12];
    const float* bhh  = (const float*)d_in[13];
    const float* Wa   = (const float*)d_in[14];
    const float* ba   = (const float*)d_in[15];
    const float* Wc   = (const float*)d_in[16];
    const float* bc   = (const float*)d_in[17];

    k_prep<<<256, 256>>>(W1, W2, W3, Wih, Whh, Wa, ba, Wc, bc, bih, bhh);
    k_enc<<<NROW/16, 256>>>(x, b1, b2, b3);
    dim3 gxg(NROW/64, 4);
    k_xg<<<gxg, 256>>>();
    k_rec<<<128, 512>>>(done, h0, c0);
    k_head<<<NROW/64, 256>>>((float*)d_out);
}

// round 5
// speedup vs baseline: 1.1307x; 1.1307x over previous
#include <cuda_runtime.h>

// Problem dims (fixed by the dataset)
#define TT 256
#define BB 1024
#define NROW (TT*BB)   // 262144

#define KREG 56        // WhhT k-slices held in registers per thread
#define KSMEM 72       // WhhT k-slices held in shared memory

typedef unsigned long long u64;

// -------- device scratch (no allocations allowed) --------
__device__ float g_hid[(size_t)NROW * 128];   // encoder output        134MB
__device__ float g_xg [(size_t)NROW * 512];   // x@Wih.T + bih + bhh   537MB
__device__ float g_w1t [128 * 128];           // W1 transposed [k][o]
__device__ float g_w2t [128 * 32];
__device__ float g_w3t [32 * 128];
__device__ float g_wihT[128 * 512];
__device__ float g_whhT[128 * 512];
__device__ float g_whead[19 * 128];           // [Wa;Wc]
__device__ float g_bhead[19];
__device__ float g_biasg[512];                // bih + bhh

// -------- packed f32x2 helpers --------
__device__ __forceinline__ u64 pk2(float lo, float hi) {
    u64 r; asm("mov.b64 %0,{%1,%2};" : "=l"(r) : "f"(lo), "f"(hi)); return r;
}
__device__ __forceinline__ u64 dup2(float v) { return pk2(v, v); }
__device__ __forceinline__ void upk(u64 p, float& lo, float& hi) {
    asm("mov.b64 {%0,%1},%2;" : "=f"(lo), "=f"(hi) : "l"(p));
}
__device__ __forceinline__ u64 ffma2(u64 a, u64 b, u64 c) {
    u64 d; asm("fma.rn.f32x2 %0,%1,%2,%3;" : "=l"(d) : "l"(a), "l"(b), "l"(c)); return d;
}
__device__ __forceinline__ u64 fmul2(u64 a, u64 b) {
    u64 d; asm("mul.rn.f32x2 %0,%1,%2;" : "=l"(d) : "l"(a), "l"(b)); return d;
}
__device__ __forceinline__ float sig_f(float v) {
    return __fdividef(1.f, 1.f + __expf(-v));
}
__device__ __forceinline__ float tanh_f(float v) {
    return 2.f * sig_f(2.f * v) - 1.f;
}

// -------- prep: transpose weights, fold biases --------
__global__ void k_prep(const float* __restrict__ W1, const float* __restrict__ W2,
                       const float* __restrict__ W3, const float* __restrict__ Wih,
                       const float* __restrict__ Whh, const float* __restrict__ Wa,
                       const float* __restrict__ ba, const float* __restrict__ Wc,
                       const float* __restrict__ bc, const float* __restrict__ bih,
                       const float* __restrict__ bhh)
{
    int i0 = blockIdx.x * blockDim.x + threadIdx.x;
    int stride = gridDim.x * blockDim.x;
    for (int i = i0; i < 128*128; i += stride) { int k = i >> 7, o = i & 127; g_w1t[i] = W1[o*128 + k]; }
    for (int i = i0; i < 128*32;  i += stride) { int k = i / 32, o = i % 32;  g_w2t[i] = W2[o*128 + k]; }
    for (int i = i0; i < 32*128;  i += stride) { int k = i >> 7, o = i & 127; g_w3t[i] = W3[o*32  + k]; }
    for (int i = i0; i < 128*512; i += stride) { int k = i >> 9, o = i & 511; g_wihT[i] = Wih[o*128 + k]; }
    for (int i = i0; i < 128*512; i += stride) { int k = i >> 9, o = i & 511; g_whhT[i] = Whh[o*128 + k]; }
    for (int i = i0; i < 19*128;  i += stride) { int o = i >> 7, k = i & 127; g_whead[i] = (o < 18) ? Wa[o*128 + k] : Wc[k]; }
    for (int i = i0; i < 19;      i += stride) g_bhead[i] = (i < 18) ? ba[i] : bc[0];
    for (int i = i0; i < 512;     i += stride) g_biasg[i] = bih[i] + bhh[i];
}

// -------- fused 3-layer MLP encoder: 16 rows/block --------
__global__ void __launch_bounds__(256) k_enc(const float* __restrict__ x,
    const float* __restrict__ b1, const float* __restrict__ b2, const float* __restrict__ b3)
{
    __shared__ float xs [16][132];
    __shared__ float h1s[16][132];
    __shared__ float h2s[16][36];
    int tid = threadIdx.x;
    size_t row0 = (size_t)blockIdx.x * 16;
    for (int i = tid; i < 16*128; i += 256) { int r = i >> 7, k = i & 127; xs[r][k] = x[(row0 + r)*128 + k]; }
    __syncthreads();
    int tx = tid & 15, ty = tid >> 4;
    int c0 = tx * 8;
    // stage 1: relu(x @ W1T + b1) -> h1s [16][128]
    {
        u64 acc[4];
        ulonglong2 bb0 = *(const ulonglong2*)&b1[c0];
        ulonglong2 bb1 = *(const ulonglong2*)&b1[c0 + 4];
        acc[0] = bb0.x; acc[1] = bb0.y; acc[2] = bb1.x; acc[3] = bb1.y;
        #pragma unroll 8
        for (int k = 0; k < 128; k++) {
            ulonglong2 w0 = *(const ulonglong2*)&g_w1t[k*128 + c0];
            ulonglong2 w1 = *(const ulonglong2*)&g_w1t[k*128 + c0 + 4];
            u64 A = dup2(xs[ty][k]);
            acc[0] = ffma2(A, w0.x, acc[0]); acc[1] = ffma2(A, w0.y, acc[1]);
            acc[2] = ffma2(A, w1.x, acc[2]); acc[3] = ffma2(A, w1.y, acc[3]);
        }
        #pragma unroll
        for (int cp = 0; cp < 4; cp++) {
            float lo, hi; upk(acc[cp], lo, hi);
            h1s[ty][c0 + 2*cp]     = fmaxf(lo, 0.f);
            h1s[ty][c0 + 2*cp + 1] = fmaxf(hi, 0.f);
        }
    }
    __syncthreads();
    // stage 2: relu(h1 @ W2T + b2) -> h2s [16][32]
    {
        int r = tid >> 4;          // 0..15
        int c = (tid & 15) * 2;    // 0..30
        u64 acc = *(const u64*)&b2[c];
        #pragma unroll 8
        for (int k = 0; k < 128; k++) {
            u64 w = *(const u64*)&g_w2t[k*32 + c];
            u64 A = dup2(h1s[r][k]);
            acc = ffma2(A, w, acc);
        }
        float lo, hi; upk(acc, lo, hi);
        h2s[r][c] = fmaxf(lo, 0.f); h2s[r][c + 1] = fmaxf(hi, 0.f);
    }
    __syncthreads();
    // stage 3: relu(h2 @ W3T + b3) -> g_hid [16][128]
    {
        u64 acc[4];
        ulonglong2 bb0 = *(const ulonglong2*)&b3[c0];
        ulonglong2 bb1 = *(const ulonglong2*)&b3[c0 + 4];
        acc[0] = bb0.x; acc[1] = bb0.y; acc[2] = bb1.x; acc[3] = bb1.y;
        #pragma unroll
        for (int k = 0; k < 32; k++) {
            ulonglong2 w0 = *(const ulonglong2*)&g_w3t[k*128 + c0];
            ulonglong2 w1 = *(const ulonglong2*)&g_w3t[k*128 + c0 + 4];
            u64 A = dup2(h2s[ty][k]);
            acc[0] = ffma2(A, w0.x, acc[0]); acc[1] = ffma2(A, w0.y, acc[1]);
            acc[2] = ffma2(A, w1.x, acc[2]); acc[3] = ffma2(A, w1.y, acc[3]);
        }
        float* dst = &g_hid[(row0 + ty)*128 + c0];
        #pragma unroll
        for (int cp = 0; cp < 4; cp++) {
            float lo, hi; upk(acc[cp], lo, hi);
            *(float2*)&dst[2*cp] = make_float2(fmaxf(lo, 0.f), fmaxf(hi, 0.f));
        }
    }
}

// -------- xg = hid @ WihT + (bih+bhh): 64 rows x 128 cols per block --------
__global__ void __launch_bounds__(256) k_xg()
{
    __shared__ float As[64][132];
    int tid = threadIdx.x;
    size_t row0 = (size_t)blockIdx.x * 64;
    int cb = blockIdx.y * 128;
    for (int i = tid; i < 64*128; i += 256) { int r = i >> 7, k = i & 127; As[r][k] = g_hid[(row0 + r)*128 + k]; }
    __syncthreads();
    int tx = tid & 15, ty = tid >> 4;
    int c0 = cb + tx * 8;
    u64 acc[4][4];
    {
        ulonglong2 bb0 = *(const ulonglong2*)&g_biasg[c0];
        ulonglong2 bb1 = *(const ulonglong2*)&g_biasg[c0 + 4];
        #pragma unroll
        for (int i = 0; i < 4; i++) { acc[i][0] = bb0.x; acc[i][1] = bb0.y; acc[i][2] = bb1.x; acc[i][3] = bb1.y; }
    }
    #pragma unroll 4
    for (int k = 0; k < 128; k++) {
        ulonglong2 w0 = *(const ulonglong2*)&g_wihT[k*512 + c0];
        ulonglong2 w1 = *(const ulonglong2*)&g_wihT[k*512 + c0 + 4];
        #pragma unroll
        for (int i = 0; i < 4; i++) {
            u64 A = dup2(As[ty*4 + i][k]);
            acc[i][0] = ffma2(A, w0.x, acc[i][0]); acc[i][1] = ffma2(A, w0.y, acc[i][1]);
            acc[i][2] = ffma2(A, w1.x, acc[i][2]); acc[i][3] = ffma2(A, w1.y, acc[i][3]);
        }
    }
    #pragma unroll
    for (int i = 0; i < 4; i++) {
        float* dst = &g_xg[(row0 + ty*4 + i)*512 + c0];
        #pragma unroll
        for (int cp = 0; cp < 4; cp++) {
            float lo, hi; upk(acc[i][cp], lo, hi);
            *(float2*)&dst[2*cp] = make_float2(lo, hi);
        }
    }
}

// -------- LSTM recurrence + fused head --------
// 8 batch elems/block (4 packed pairs), 128 blocks, weight-stationary WhhT:
// thread j owns gate column j; KREG k-slices in registers, KSMEM in smem.
struct __align__(16) RecSmem {
    float2 act[4][512];          // activated gates, [pair][gate]  16KB
    float2 hsm[128][4];          // h (masked for next step)        4KB
    float  wsm[KSMEM][512];      // WhhT k=KREG..127              144KB
    float  hout[2][8][128];      // unmasked h double buffer        8KB
    float  whead[19][132];       // head weights (padded rows)     ~10KB
    float  bhead[20];
    float  dmask[2][8];          // (1-done) double buffer
};

__global__ void __launch_bounds__(512, 1) k_rec(const float* __restrict__ done,
    const float* __restrict__ h0, const float* __restrict__ c0,
    float* __restrict__ out)
{
    extern __shared__ char smraw[];
    RecSmem& sm = *(RecSmem*)smraw;
    int j = threadIdx.x;
    int base = blockIdx.x * 8;

    // ---- load weights: registers (k < KREG) + smem (rest) ----
    float wreg[KREG];
    #pragma unroll
    for (int k = 0; k < KREG; k++) wreg[k] = g_whhT[k*512 + j];
    for (int i = j; i < KSMEM*512; i += 512) {
        int k = i >> 9, c = i & 511;
        sm.wsm[k][c] = g_whhT[(KREG + k)*512 + c];
    }
    for (int i = j; i < 19*128; i += 512) sm.whead[i >> 7][i & 127] = g_whead[i];
    if (j < 19) sm.bhead[j] = g_bhead[j];
    if (j < 8)  sm.dmask[0][j] = 1.0f - done[base + j];

    // ---- init h (pre-masked with m_0) and c ----
    u64 c2[4];
    if (j < 128) {
        #pragma unroll
        for (int p = 0; p < 4; p++) {
            int b0 = base + 2*p;
            float m0 = 1.0f - done[b0], m1 = 1.0f - done[b0 + 1];
            sm.hsm[j][p] = make_float2(h0[b0*128 + j] * m0, h0[(b0+1)*128 + j] * m1);
            c2[p] = pk2(c0[b0*128 + j], c0[(b0+1)*128 + j]);
        }
    }
    // prefetch xg[0]
    u64 xv[4];
    {
        const float* xr = g_xg + (size_t)base * 512 + j;
        #pragma unroll
        for (int p = 0; p < 4; p++) xv[p] = pk2(xr[(2*p)*512], xr[(2*p + 1)*512]);
    }
    __syncthreads();

    bool is_g = (j >= 256) && (j < 384);   // tanh gate

    for (int t = 0; t < TT; t++) {
        // ---- phase 1: gates = xg[t] + h @ WhhT ----
        u64 acc[4];
        #pragma unroll
        for (int p = 0; p < 4; p++) acc[p] = xv[p];
        {   // prefetch xg[t+1] + done[t+1] (covered by the k-loop below)
            int tn = (t + 1 < TT) ? (t + 1) : t;
            const float* xr = g_xg + ((size_t)tn * BB + base) * 512 + j;
            #pragma unroll
            for (int p = 0; p < 4; p++) xv[p] = pk2(xr[(2*p)*512], xr[(2*p + 1)*512]);
            if (j < 8) sm.dmask[(t + 1) & 1][j] = 1.0f - done[(size_t)tn * BB + base + j];
        }
        #pragma unroll
        for (int k = 0; k < KREG; k++) {
            u64 W = dup2(wreg[k]);
            ulonglong2 h01 = *(const ulonglong2*)&sm.hsm[k][0];
            ulonglong2 h23 = *(const ulonglong2*)&sm.hsm[k][2];
            acc[0] = ffma2(W, h01.x, acc[0]); acc[1] = ffma2(W, h01.y, acc[1]);
            acc[2] = ffma2(W, h23.x, acc[2]); acc[3] = ffma2(W, h23.y, acc[3]);
        }
        #pragma unroll
        for (int k = 0; k < KSMEM; k++) {
            u64 W = dup2(sm.wsm[k][j]);
            ulonglong2 h01 = *(const ulonglong2*)&sm.hsm[KREG + k][0];
            ulonglong2 h23 = *(const ulonglong2*)&sm.hsm[KREG + k][2];
            acc[0] = ffma2(W, h01.x, acc[0]); acc[1] = ffma2(W, h01.y, acc[1]);
            acc[2] = ffma2(W, h23.x, acc[2]); acc[3] = ffma2(W, h23.y, acc[3]);
        }
        #pragma unroll
        for (int p = 0; p < 4; p++) {
            float lo, hi; upk(acc[p], lo, hi);
            if (is_g) { lo = tanh_f(lo); hi = tanh_f(hi); }
            else      { lo = sig_f(lo);  hi = sig_f(hi);  }
            sm.act[p][j] = make_float2(lo, hi);
        }
        __syncthreads();

        // ---- phase 2 ----
        if (j < 128) {
            // cell/h update for cell j, all 8 elems
            float4 ma = *(const float4*)&sm.dmask[t & 1][0];
            float4 mb = *(const float4*)&sm.dmask[t & 1][4];
            float4 na = *(const float4*)&sm.dmask[(t + 1) & 1][0];
            float4 nb = *(const float4*)&sm.dmask[(t + 1) & 1][4];
            float mm[8] = {ma.x, ma.y, ma.z, ma.w, mb.x, mb.y, mb.z, mb.w};
            float nn[8] = {na.x, na.y, na.z, na.w, nb.x, nb.y, nb.z, nb.w};
            float* ho = &sm.hout[t & 1][0][0];
            #pragma unroll
            for (int p = 0; p < 4; p++) {
                u64 iv = *(const u64*)&sm.act[p][j];
                u64 fv = *(const u64*)&sm.act[p][j + 128];
                u64 gv = *(const u64*)&sm.act[p][j + 256];
                u64 ov = *(const u64*)&sm.act[p][j + 384];
                c2[p] = ffma2(fv, fmul2(c2[p], pk2(mm[2*p], mm[2*p + 1])), fmul2(iv, gv));
                float cl, ch; upk(c2[p], cl, ch);
                float ol, oh; upk(ov, ol, oh);
                float hl = ol * tanh_f(cl);
                float hh = oh * tanh_f(ch);
                ho[(2*p)*128 + j]     = hl;
                ho[(2*p + 1)*128 + j] = hh;
                sm.hsm[j][p] = make_float2(hl * nn[2*p], hh * nn[2*p + 1]);
            }
        } else if (t > 0) {
            // head for step t-1 (h in hout[(t-1)&1])
            int j2 = j - 128;
            if (j2 < 152) {
                int e = j2 / 19, o = j2 - e * 19;
                const float* hv = sm.hout[(t - 1) & 1][e];
                const float* wv = sm.whead[o];
                float a = sm.bhead[o];
                #pragma unroll
                for (int k = 0; k < 128; k += 4) {
                    float4 h4 = *(const float4*)&hv[k];
                    float4 w4 = *(const float4*)&wv[k];
                    a += h4.x*w4.x + h4.y*w4.y + h4.z*w4.z + h4.w*w4.w;
                }
                out[((size_t)(t - 1) * BB + base + e) * 19 + o] = a;
            }
        }
        __syncthreads();
    }

    // ---- epilogue: head for t = TT-1 ----
    if (j < 152) {
        int e = j / 19, o = j - e * 19;
        const float* hv = sm.hout[(TT - 1) & 1][e];
        const float* wv = sm.whead[o];
        float a = sm.bhead[o];
        #pragma unroll
        for (int k = 0; k < 128; k += 4) {
            float4 h4 = *(const float4*)&hv[k];
            float4 w4 = *(const float4*)&wv[k];
            a += h4.x*w4.x + h4.y*w4.y + h4.z*w4.z + h4.w*w4.w;
        }
        out[((size_t)(TT - 1) * BB + base + e) * 19 + o] = a;
    }
}

extern "C" void kernel_launch(void* const* d_in, const int* in_sizes, int n_in,
                              void* d_out, int out_size)
{
    const float* x    = (const float*)d_in[0];
    const float* done = (const float*)d_in[1];
    const float* h0   = (const float*)d_in[2];
    const float* c0   = (const float*)d_in[3];
    const float* W1   = (const float*)d_in[4];
    const float* b1   = (const float*)d_in[5];
    const float* W2   = (const float*)d_in[6];
    const float* b2   = (const float*)d_in[7];
    const float* W3   = (const float*)d_in[8];
    const float* b3   = (const float*)d_in[9];
    const float* Wih  = (const float*)d_in[10];
    const float* Whh  = (const float*)d_in[11];
    const float* bih  = (const float*)d_in[12];
    const float* bhh  = (const float*)d_in[13];
    const float* Wa   = (const float*)d_in[14];
    const float* ba   = (const float*)d_in[15];
    const float* Wc   = (const float*)d_in[16];
    const float* bc   = (const float*)d_in[17];

    int rec_smem = (int)sizeof(RecSmem);
    cudaFuncSetAttribute(k_rec, cudaFuncAttributeMaxDynamicSharedMemorySize, rec_smem);

    k_prep<<<256, 256>>>(W1, W2, W3, Wih, Whh, Wa, ba, Wc, bc, bih, bhh);
    k_enc<<<NROW/16, 256>>>(x, b1, b2, b3);
    dim3 gxg(NROW/64, 4);
    k_xg<<<gxg, 256>>>();
    k_rec<<<128, 512, rec_smem>>>(done, h0, c0, (float*)d_out);
}

// round 7
// speedup vs baseline: 1.3472x; 1.1914x over previous
#include <cuda_runtime.h>
#include <cuda_bf16.h>
#include <cstdint>

// Problem dims (fixed by the dataset)
#define TT 256
#define BB 1024
#define NROW (TT*BB)   // 262144

#define KREG 40        // WhhT k-slices held in registers per thread (fits 128-reg cap)
#define KSMEM 88       // WhhT k-slices held in shared memory

typedef unsigned long long u64;

// -------- device scratch (no allocations allowed) --------
__device__ __nv_bfloat16 g_hid_hi[(size_t)NROW * 128];  // encoder out, bf16 hi   64MB
__device__ __nv_bfloat16 g_hid_lo[(size_t)NROW * 128];  // encoder out, bf16 lo   64MB
__device__ float g_xg [(size_t)NROW * 512];             // x@Wih.T + bias        537MB
__device__ float g_w1t [128 * 128];                     // W1 transposed [k][o]
__device__ float g_w2t [128 * 32];
__device__ float g_w3t [32 * 128];
__device__ float g_whhT[128 * 512];
__device__ float g_whead[19 * 128];                     // [Wa;Wc]
__device__ float g_bhead[19];
__device__ float g_biasg[512];                          // bih + bhh
__device__ __nv_bfloat16 g_wbhi[512 * 128];             // Wih bf16 hi  [gate][k]
__device__ __nv_bfloat16 g_wblo[512 * 128];             // Wih bf16 lo  [gate][k]

// -------- PTX helpers --------
__device__ __forceinline__ uint32_t smem_to_u32(const void* p) {
    uint32_t a;
    asm("{ .reg .u64 t; cvta.to.shared.u64 t, %1; cvt.u32.u64 %0, t; }" : "=r"(a) : "l"(p));
    return a;
}
__device__ __forceinline__ void ldsm4(uint32_t& r0, uint32_t& r1, uint32_t& r2, uint32_t& r3,
                                      uint32_t addr) {
    asm volatile("ldmatrix.sync.aligned.m8n8.x4.shared.b16 {%0,%1,%2,%3}, [%4];"
                 : "=r"(r0), "=r"(r1), "=r"(r2), "=r"(r3) : "r"(addr));
}
__device__ __forceinline__ void mma16816(float* d, const uint32_t* a, const uint32_t* b) {
    asm volatile(
        "mma.sync.aligned.m16n8k16.row.col.f32.bf16.bf16.f32 "
        "{%0,%1,%2,%3},{%4,%5,%6,%7},{%8,%9},{%0,%1,%2,%3};"
        : "+f"(d[0]), "+f"(d[1]), "+f"(d[2]), "+f"(d[3])
        : "r"(a[0]), "r"(a[1]), "r"(a[2]), "r"(a[3]), "r"(b[0]), "r"(b[1]));
}

// -------- packed f32x2 helpers --------
__device__ __forceinline__ u64 pk2(float lo, float hi) {
    u64 r; asm("mov.b64 %0,{%1,%2};" : "=l"(r) : "f"(lo), "f"(hi)); return r;
}
__device__ __forceinline__ u64 dup2(float v) { return pk2(v, v); }
__device__ __forceinline__ void upk(u64 p, float& lo, float& hi) {
    asm("mov.b64 {%0,%1},%2;" : "=f"(lo), "=f"(hi) : "l"(p));
}
__device__ __forceinline__ u64 ffma2(u64 a, u64 b, u64 c) {
    u64 d; asm("fma.rn.f32x2 %0,%1,%2,%3;" : "=l"(d) : "l"(a), "l"(b), "l"(c)); return d;
}
__device__ __forceinline__ u64 fmul2(u64 a, u64 b) {
    u64 d; asm("mul.rn.f32x2 %0,%1,%2;" : "=l"(d) : "l"(a), "l"(b)); return d;
}
__device__ __forceinline__ float sig_f(float v) {
    return __fdividef(1.f, 1.f + __expf(-v));
}
__device__ __forceinline__ float tanh_f(float v) {
    return 2.f * sig_f(2.f * v) - 1.f;
}

// -------- prep: transpose weights, fold biases, bf16 hi/lo Wih --------
__global__ void k_prep(const float* __restrict__ W1, const float* __restrict__ W2,
                       const float* __restrict__ W3, const float* __restrict__ Wih,
                       const float* __restrict__ Whh, const float* __restrict__ Wa,
                       const float* __restrict__ ba, const float* __restrict__ Wc,
                       const float* __restrict__ bc, const float* __restrict__ bih,
                       const float* __restrict__ bhh)
{
    int i0 = blockIdx.x * blockDim.x + threadIdx.x;
    int stride = gridDim.x * blockDim.x;
    for (int i = i0; i < 128*128; i += stride) { int k = i >> 7, o = i & 127; g_w1t[i] = W1[o*128 + k]; }
    for (int i = i0; i < 128*32;  i += stride) { int k = i / 32, o = i % 32;  g_w2t[i] = W2[o*128 + k]; }
    for (int i = i0; i < 32*128;  i += stride) { int k = i >> 7, o = i & 127; g_w3t[i] = W3[o*32  + k]; }
    for (int i = i0; i < 128*512; i += stride) { int k = i >> 9, o = i & 511; g_whhT[i] = Whh[o*128 + k]; }
    for (int i = i0; i < 19*128;  i += stride) { int o = i >> 7, k = i & 127; g_whead[i] = (o < 18) ? Wa[o*128 + k] : Wc[k]; }
    for (int i = i0; i < 19;      i += stride) g_bhead[i] = (i < 18) ? ba[i] : bc[0];
    for (int i = i0; i < 512;     i += stride) g_biasg[i] = bih[i] + bhh[i];
    for (int i = i0; i < 512*128; i += stride) {
        float w = Wih[i];
        __nv_bfloat16 hb = __float2bfloat16(w);
        g_wbhi[i] = hb;
        g_wblo[i] = __float2bfloat16(w - __bfloat162float(hb));
    }
}

// -------- fused 3-layer MLP encoder: 16 rows/block, bf16 hi/lo output --------
__global__ void __launch_bounds__(256) k_enc(const float* __restrict__ x,
    const float* __restrict__ b1, const float* __restrict__ b2, const float* __restrict__ b3)
{
    __shared__ float xs [16][132];
    __shared__ float h1s[16][132];
    __shared__ float h2s[16][36];
    int tid = threadIdx.x;
    size_t row0 = (size_t)blockIdx.x * 16;
    for (int i = tid; i < 16*128; i += 256) { int r = i >> 7, k = i & 127; xs[r][k] = x[(row0 + r)*128 + k]; }
    __syncthreads();
    int tx = tid & 15, ty = tid >> 4;
    int c0 = tx * 8;
    // stage 1: relu(x @ W1T + b1)
    {
        u64 acc[4];
        ulonglong2 bb0 = *(const ulonglong2*)&b1[c0];
        ulonglong2 bb1 = *(const ulonglong2*)&b1[c0 + 4];
        acc[0] = bb0.x; acc[1] = bb0.y; acc[2] = bb1.x; acc[3] = bb1.y;
        #pragma unroll 8
        for (int k = 0; k < 128; k++) {
            ulonglong2 w0 = *(const ulonglong2*)&g_w1t[k*128 + c0];
            ulonglong2 w1 = *(const ulonglong2*)&g_w1t[k*128 + c0 + 4];
            u64 A = dup2(xs[ty][k]);
            acc[0] = ffma2(A, w0.x, acc[0]); acc[1] = ffma2(A, w0.y, acc[1]);
            acc[2] = ffma2(A, w1.x, acc[2]); acc[3] = ffma2(A, w1.y, acc[3]);
        }
        #pragma unroll
        for (int cp = 0; cp < 4; cp++) {
            float lo, hi; upk(acc[cp], lo, hi);
            h1s[ty][c0 + 2*cp]     = fmaxf(lo, 0.f);
            h1s[ty][c0 + 2*cp + 1] = fmaxf(hi, 0.f);
        }
    }
    __syncthreads();
    // stage 2: relu(h1 @ W2T + b2)
    {
        int r = tid >> 4;
        int c = (tid & 15) * 2;
        u64 acc = *(const u64*)&b2[c];
        #pragma unroll 8
        for (int k = 0; k < 128; k++) {
            u64 w = *(const u64*)&g_w2t[k*32 + c];
            u64 A = dup2(h1s[r][k]);
            acc = ffma2(A, w, acc);
        }
        float lo, hi; upk(acc, lo, hi);
        h2s[r][c] = fmaxf(lo, 0.f); h2s[r][c + 1] = fmaxf(hi, 0.f);
    }
    __syncthreads();
    // stage 3: relu(h2 @ W3T + b3) -> bf16 hi/lo
    {
        u64 acc[4];
        ulonglong2 bb0 = *(const ulonglong2*)&b3[c0];
        ulonglong2 bb1 = *(const ulonglong2*)&b3[c0 + 4];
        acc[0] = bb0.x; acc[1] = bb0.y; acc[2] = bb1.x; acc[3] = bb1.y;
        #pragma unroll
        for (int k = 0; k < 32; k++) {
            ulonglong2 w0 = *(const ulonglong2*)&g_w3t[k*128 + c0];
            ulonglong2 w1 = *(const ulonglong2*)&g_w3t[k*128 + c0 + 4];
            u64 A = dup2(h2s[ty][k]);
            acc[0] = ffma2(A, w0.x, acc[0]); acc[1] = ffma2(A, w0.y, acc[1]);
            acc[2] = ffma2(A, w1.x, acc[2]); acc[3] = ffma2(A, w1.y, acc[3]);
        }
        __align__(16) __nv_bfloat16 hv[8];
        __align__(16) __nv_bfloat16 lv[8];
        #pragma unroll
        for (int cp = 0; cp < 4; cp++) {
            float lo, hi; upk(acc[cp], lo, hi);
            lo = fmaxf(lo, 0.f); hi = fmaxf(hi, 0.f);
            __nv_bfloat16 h0b = __float2bfloat16(lo);
            __nv_bfloat16 h1b = __float2bfloat16(hi);
            hv[2*cp]   = h0b; hv[2*cp+1] = h1b;
            lv[2*cp]   = __float2bfloat16(lo - __bfloat162float(h0b));
            lv[2*cp+1] = __float2bfloat16(hi - __bfloat162float(h1b));
        }
        size_t off = (row0 + ty) * 128 + c0;
        *(uint4*)&g_hid_hi[off] = *(const uint4*)hv;
        *(uint4*)&g_hid_lo[off] = *(const uint4*)lv;
    }
}

// -------- xg = hid @ WihT + bias via mma.sync bf16 hi/lo split --------
// CTA: M=128 rows x N=128 gates; 8 warps, warp tile 32x64.
// 3 passes over K=128: Ahi*Whi + Ahi*Wlo + Alo*Whi (lo*lo dropped, ~1e-6).
#define ASTR 136                          // bf16 elems per smem row (16B padded)
#define XG_TILE_BYTES (128 * ASTR * 2)    // 34816
#define XG_DYN_SMEM (4 * XG_TILE_BYTES + 512 + 16)

__global__ void __launch_bounds__(256) k_xgmma()
{
    extern __shared__ char dyn[];
    __nv_bfloat16* smb = (__nv_bfloat16*)dyn;
    float* sbias = (float*)(dyn + 4 * XG_TILE_BYTES);
    int tid = threadIdx.x;
    int wid = tid >> 5, lane = tid & 31;
    size_t row0 = (size_t)blockIdx.x * 128;
    int col0 = blockIdx.y * 128;

    // smem layout: [0]=Ahi [1]=Alo [2]=Bhi [3]=Blo, each 128 rows x ASTR bf16
    // fill tiles (uint4 = 8 bf16)
    for (int i = tid; i < 128 * 16; i += 256) {
        int r = i >> 4, v = i & 15;
        size_t goff = (row0 + r) * 128 + v * 8;
        int soff = r * ASTR + v * 8;
        *(uint4*)&smb[soff]              = *(const uint4*)&g_hid_hi[goff];
        *(uint4*)&smb[128*ASTR + soff]   = *(const uint4*)&g_hid_lo[goff];
        size_t woff = (size_t)(col0 + r) * 128 + v * 8;
        *(uint4*)&smb[2*128*ASTR + soff] = *(const uint4*)&g_wbhi[woff];
        *(uint4*)&smb[3*128*ASTR + soff] = *(const uint4*)&g_wblo[woff];
    }
    if (tid < 128) sbias[tid] = g_biasg[col0 + tid];
    __syncthreads();

    uint32_t smbase = smem_to_u32(smb);
    int wm = (wid & 3) * 32;        // warp m offset (0..96)
    int wn = (wid >> 2) * 64;       // warp n offset (0 or 64)
    int sub = lane >> 3, rowl = lane & 7;

    float acc[2][8][4];
    #pragma unroll
    for (int mt = 0; mt < 2; mt++)
        #pragma unroll
        for (int nt = 0; nt < 8; nt++)
            #pragma unroll
            for (int q = 0; q < 4; q++) acc[mt][nt][q] = 0.f;

    const uint32_t aBase[3] = {0u, 0u, (uint32_t)XG_TILE_BYTES};
    const uint32_t bBase[3] = {2u*XG_TILE_BYTES, 3u*XG_TILE_BYTES, 2u*XG_TILE_BYTES};

    // per-lane ldmatrix row/col components
    int a_row_part = (sub & 1) * 8 + rowl;     // + mt*16 + wm
    int a_col_part = (sub >> 1) * 8;           // + kc*16
    int b_row_part = (sub >> 1) * 8 + rowl;    // + np*16 + wn
    int b_col_part = (sub & 1) * 8;            // + kc*16

    #pragma unroll
    for (int pass = 0; pass < 3; pass++) {
        uint32_t aB = smbase + aBase[pass];
        uint32_t bB = smbase + bBase[pass];
        #pragma unroll
        for (int kc = 0; kc < 8; kc++) {
            uint32_t af[2][4];
            #pragma unroll
            for (int mt = 0; mt < 2; mt++) {
                uint32_t addr = aB + ((wm + mt*16 + a_row_part) * ASTR + kc*16 + a_col_part) * 2;
                ldsm4(af[mt][0], af[mt][1], af[mt][2], af[mt][3], addr);
            }
            uint32_t bf_[8][2];
            #pragma unroll
            for (int np = 0; np < 4; np++) {
                uint32_t addr = bB + ((wn + np*16 + b_row_part) * ASTR + kc*16 + b_col_part) * 2;
                uint32_t r0, r1, r2, r3;
                ldsm4(r0, r1, r2, r3, addr);
                bf_[np*2][0] = r0; bf_[np*2][1] = r1;
                bf_[np*2+1][0] = r2; bf_[np*2+1][1] = r3;
            }
            #pragma unroll
            for (int mt = 0; mt < 2; mt++)
                #pragma unroll
                for (int nt = 0; nt < 8; nt++)
                    mma16816(acc[mt][nt], af[mt], bf_[nt]);
        }
    }

    // store D + bias -> g_xg
    int g = lane >> 2, tg = lane & 3;
    #pragma unroll
    for (int mt = 0; mt < 2; mt++) {
        size_t r_top = row0 + wm + mt*16 + g;
        #pragma unroll
        for (int nt = 0; nt < 8; nt++) {
            int cl = wn + nt*8 + tg*2;
            float b0 = sbias[cl], b1 = sbias[cl + 1];
            float* o0 = &g_xg[r_top * 512 + col0 + cl];
            *(float2*)o0 = make_float2(acc[mt][nt][0] + b0, acc[mt][nt][1] + b1);
            float* o1 = &g_xg[(r_top + 8) * 512 + col0 + cl];
            *(float2*)o1 = make_float2(acc[mt][nt][2] + b0, acc[mt][nt][3] + b1);
        }
    }
}

// -------- LSTM recurrence + fused head --------
struct __align__(16) RecSmem {
    float2 act[4][512];          // activated gates, [pair][gate]  16KB
    float2 hsm[128][4];          // h (masked for next step)        4KB
    float  wsm[KSMEM][512];      // WhhT k=KREG..127              176KB
    float  hout[2][8][128];      // unmasked h double buffer        8KB
    float  whead[19][132];       // head weights (padded rows)     ~10KB
    float  bhead[20];
    float  dmask[2][8];          // (1-done) double buffer
};

__global__ void __launch_bounds__(512, 1) k_rec(const float* __restrict__ done,
    const float* __restrict__ h0, const float* __restrict__ c0,
    float* __restrict__ out)
{
    extern __shared__ char smraw[];
    RecSmem& sm = *(RecSmem*)smraw;
    int j = threadIdx.x;
    int base = blockIdx.x * 8;

    float wreg[KREG];
    #pragma unroll
    for (int k = 0; k < KREG; k++) wreg[k] = g_whhT[k*512 + j];
    for (int i = j; i < KSMEM*512; i += 512) {
        int k = i >> 9, c = i & 511;
        sm.wsm[k][c] = g_whhT[(KREG + k)*512 + c];
    }
    for (int i = j; i < 19*128; i += 512) sm.whead[i >> 7][i & 127] = g_whead[i];
    if (j < 19) sm.bhead[j] = g_bhead[j];
    if (j < 8)  sm.dmask[0][j] = 1.0f - done[base + j];

    u64 c2[4];
    if (j < 128) {
        #pragma unroll
        for (int p = 0; p < 4; p++) {
            int b0 = base + 2*p;
            float m0 = 1.0f - done[b0], m1 = 1.0f - done[b0 + 1];
            sm.hsm[j][p] = make_float2(h0[b0*128 + j] * m0, h0[(b0+1)*128 + j] * m1);
            c2[p] = pk2(c0[b0*128 + j], c0[(b0+1)*128 + j]);
        }
    }
    u64 xv[4];
    {
        const float* xr = g_xg + (size_t)base * 512 + j;
        #pragma unroll
        for (int p = 0; p < 4; p++) xv[p] = pk2(xr[(2*p)*512], xr[(2*p + 1)*512]);
    }
    __syncthreads();

    bool is_g = (j >= 256) && (j < 384);

    for (int t = 0; t < TT; t++) {
        u64 acc[4];
        #pragma unroll
        for (int p = 0; p < 4; p++) acc[p] = xv[p];
        {
            int tn = (t + 1 < TT) ? (t + 1) : t;
            const float* xr = g_xg + ((size_t)tn * BB + base) * 512 + j;
            #pragma unroll
            for (int p = 0; p < 4; p++) xv[p] = pk2(xr[(2*p)*512], xr[(2*p + 1)*512]);
            if (j < 8) sm.dmask[(t + 1) & 1][j] = 1.0f - done[(size_t)tn * BB + base + j];
        }
        #pragma unroll
        for (int k = 0; k < KREG; k++) {
            u64 W = dup2(wreg[k]);
            ulonglong2 h01 = *(const ulonglong2*)&sm.hsm[k][0];
            ulonglong2 h23 = *(const ulonglong2*)&sm.hsm[k][2];
            acc[0] = ffma2(W, h01.x, acc[0]); acc[1] = ffma2(W, h01.y, acc[1]);
            acc[2] = ffma2(W, h23.x, acc[2]); acc[3] = ffma2(W, h23.y, acc[3]);
        }
        #pragma unroll
        for (int k = 0; k < KSMEM; k++) {
            u64 W = dup2(sm.wsm[k][j]);
            ulonglong2 h01 = *(const ulonglong2*)&sm.hsm[KREG + k][0];
            ulonglong2 h23 = *(const ulonglong2*)&sm.hsm[KREG + k][2];
            acc[0] = ffma2(W, h01.x, acc[0]); acc[1] = ffma2(W, h01.y, acc[1]);
            acc[2] = ffma2(W, h23.x, acc[2]); acc[3] = ffma2(W, h23.y, acc[3]);
        }
        #pragma unroll
        for (int p = 0; p < 4; p++) {
            float lo, hi; upk(acc[p], lo, hi);
            if (is_g) { lo = tanh_f(lo); hi = tanh_f(hi); }
            else      { lo = sig_f(lo);  hi = sig_f(hi);  }
            sm.act[p][j] = make_float2(lo, hi);
        }
        __syncthreads();

        if (j < 128) {
            float4 ma = *(const float4*)&sm.dmask[t & 1][0];
            float4 mb = *(const float4*)&sm.dmask[t & 1][4];
            float4 na = *(const float4*)&sm.dmask[(t + 1) & 1][0];
            float4 nb = *(const float4*)&sm.dmask[(t + 1) & 1][4];
            float mm[8] = {ma.x, ma.y, ma.z, ma.w, mb.x, mb.y, mb.z, mb.w};
            float nn[8] = {na.x, na.y, na.z, na.w, nb.x, nb.y, nb.z, nb.w};
            float* ho = &sm.hout[t & 1][0][0];
            #pragma unroll
            for (int p = 0; p < 4; p++) {
                u64 iv = *(const u64*)&sm.act[p][j];
                u64 fv = *(const u64*)&sm.act[p][j + 128];
                u64 gv = *(const u64*)&sm.act[p][j + 256];
                u64 ov = *(const u64*)&sm.act[p][j + 384];
                c2[p] = ffma2(fv, fmul2(c2[p], pk2(mm[2*p], mm[2*p + 1])), fmul2(iv, gv));
                float cl, ch; upk(c2[p], cl, ch);
                float ol, oh; upk(ov, ol, oh);
                float hl = ol * tanh_f(cl);
                float hh = oh * tanh_f(ch);
                ho[(2*p)*128 + j]     = hl;
                ho[(2*p + 1)*128 + j] = hh;
                sm.hsm[j][p] = make_float2(hl * nn[2*p], hh * nn[2*p + 1]);
            }
        } else if (t > 0) {
            int j2 = j - 128;
            if (j2 < 152) {
                int e = j2 / 19, o = j2 - e * 19;
                const float* hv = sm.hout[(t - 1) & 1][e];
                const float* wv = sm.whead[o];
                float a = sm.bhead[o];
                #pragma unroll
                for (int k = 0; k < 128; k += 4) {
                    float4 h4 = *(const float4*)&hv[k];
                    float4 w4 = *(const float4*)&wv[k];
                    a += h4.x*w4.x + h4.y*w4.y + h4.z*w4.z + h4.w*w4.w;
                }
                out[((size_t)(t - 1) * BB + base + e) * 19 + o] = a;
            }
        }
        __syncthreads();
    }

    if (j < 152) {
        int e = j / 19, o = j - e * 19;
        const float* hv = sm.hout[(TT - 1) & 1][e];
        const float* wv = sm.whead[o];
        float a = sm.bhead[o];
        #pragma unroll
        for (int k = 0; k < 128; k += 4) {
            float4 h4 = *(const float4*)&hv[k];
            float4 w4 = *(const float4*)&wv[k];
            a += h4.x*w4.x + h4.y*w4.y + h4.z*w4.z + h4.w*w4.w;
        }
        out[((size_t)(TT - 1) * BB + base + e) * 19 + o] = a;
    }
}

extern "C" void kernel_launch(void* const* d_in, const int* in_sizes, int n_in,
                              void* d_out, int out_size)
{
    const float* x    = (const float*)d_in[0];
    const float* done = (const float*)d_in[1];
    const float* h0   = (const float*)d_in[2];
    const float* c0   = (const float*)d_in[3];
    const float* W1   = (const float*)d_in[4];
    const float* b1   = (const float*)d_in[5];
    const float* W2   = (const float*)d_in[6];
    const float* b2   = (const float*)d_in[7];
    const float* W3   = (const float*)d_in[8];
    const float* b3   = (const float*)d_in[9];
    const float* Wih  = (const float*)d_in[10];
    const float* Whh  = (const float*)d_in[11];
    const float* bih  = (const float*)d_in[12];
    const float* bhh  = (const float*)d_in[13];
    const float* Wa   = (const float*)d_in[14];
    const float* ba   = (const float*)d_in[15];
    const float* Wc   = (const float*)d_in[16];
    const float* bc   = (const float*)d_in[17];

    int rec_smem = (int)sizeof(RecSmem);
    cudaFuncSetAttribute(k_rec, cudaFuncAttributeMaxDynamicSharedMemorySize, rec_smem);
    cudaFuncSetAttribute(k_xgmma, cudaFuncAttributeMaxDynamicSharedMemorySize, XG_DYN_SMEM);

    k_prep<<<256, 256>>>(W1, W2, W3, Wih, Whh, Wa, ba, Wc, bc, bih, bhh);
    k_enc<<<NROW/16, 256>>>(x, b1, b2, b3);
    dim3 gmm(NROW/128, 4);
    k_xgmma<<<gmm, 256, XG_DYN_SMEM>>>();
    k_rec<<<128, 512, rec_smem>>>(done, h0, c0, (float*)d_out);
}

// round 8
// speedup vs baseline: 1.8522x; 1.3749x over previous
#include <cuda_runtime.h>
#include <cuda_bf16.h>
#include <cstdint>

// Problem dims (fixed by the dataset)
#define TT 256
#define BB 1024
#define NROW (TT*BB)   // 262144

typedef unsigned long long u64;

// -------- device scratch (no allocations allowed) --------
__device__ __nv_bfloat16 g_hid_hi[(size_t)NROW * 128];  // encoder out, bf16 hi   64MB
__device__ __nv_bfloat16 g_hid_lo[(size_t)NROW * 128];  // encoder out, bf16 lo   64MB
__device__ float g_xg [(size_t)NROW * 512];             // x@Wih.T + bias        537MB
__device__ float g_w1t [128 * 128];                     // W1 transposed [k][o]
__device__ float g_w2t [128 * 32];
__device__ float g_w3t [32 * 128];
__device__ float g_whead[19 * 128];                     // [Wa;Wc]
__device__ float g_bhead[19];
__device__ float g_biasg[512];                          // bih + bhh
__device__ __nv_bfloat16 g_wbhi[512 * 128];             // Wih bf16 hi  [gate][k]
__device__ __nv_bfloat16 g_wblo[512 * 128];             // Wih bf16 lo  [gate][k]
__device__ __nv_bfloat16 g_whhbhi[512 * 128];           // Whh bf16 hi  [gate][k]
__device__ __nv_bfloat16 g_whhblo[512 * 128];           // Whh bf16 lo  [gate][k]

// -------- PTX helpers --------
__device__ __forceinline__ uint32_t smem_to_u32(const void* p) {
    uint32_t a;
    asm("{ .reg .u64 t; cvta.to.shared.u64 t, %1; cvt.u32.u64 %0, t; }" : "=r"(a) : "l"(p));
    return a;
}
__device__ __forceinline__ void ldsm4(uint32_t& r0, uint32_t& r1, uint32_t& r2, uint32_t& r3,
                                      uint32_t addr) {
    asm volatile("ldmatrix.sync.aligned.m8n8.x4.shared.b16 {%0,%1,%2,%3}, [%4];"
                 : "=r"(r0), "=r"(r1), "=r"(r2), "=r"(r3) : "r"(addr));
}
__device__ __forceinline__ void ldsm2(uint32_t& r0, uint32_t& r1, uint32_t addr) {
    asm volatile("ldmatrix.sync.aligned.m8n8.x2.shared.b16 {%0,%1}, [%2];"
                 : "=r"(r0), "=r"(r1) : "r"(addr));
}
__device__ __forceinline__ void mma16816(float* d, const uint32_t* a, const uint32_t* b) {
    asm volatile(
        "mma.sync.aligned.m16n8k16.row.col.f32.bf16.bf16.f32 "
        "{%0,%1,%2,%3},{%4,%5,%6,%7},{%8,%9},{%0,%1,%2,%3};"
        : "+f"(d[0]), "+f"(d[1]), "+f"(d[2]), "+f"(d[3])
        : "r"(a[0]), "r"(a[1]), "r"(a[2]), "r"(a[3]), "r"(b[0]), "r"(b[1]));
}

// -------- packed f32x2 helpers --------
__device__ __forceinline__ u64 pk2(float lo, float hi) {
    u64 r; asm("mov.b64 %0,{%1,%2};" : "=l"(r) : "f"(lo), "f"(hi)); return r;
}
__device__ __forceinline__ u64 dup2(float v) { return pk2(v, v); }
__device__ __forceinline__ void upk(u64 p, float& lo, float& hi) {
    asm("mov.b64 {%0,%1},%2;" : "=f"(lo), "=f"(hi) : "l"(p));
}
__device__ __forceinline__ u64 ffma2(u64 a, u64 b, u64 c) {
    u64 d; asm("fma.rn.f32x2 %0,%1,%2,%3;" : "=l"(d) : "l"(a), "l"(b), "l"(c)); return d;
}
__device__ __forceinline__ float sig_f(float v) {
    return __fdividef(1.f, 1.f + __expf(-v));
}
__device__ __forceinline__ float tanh_f(float v) {
    return 2.f * sig_f(2.f * v) - 1.f;
}

// -------- prep --------
__global__ void k_prep(const float* __restrict__ W1, const float* __restrict__ W2,
                       const float* __restrict__ W3, const float* __restrict__ Wih,
                       const float* __restrict__ Whh, const float* __restrict__ Wa,
                       const float* __restrict__ ba, const float* __restrict__ Wc,
                       const float* __restrict__ bc, const float* __restrict__ bih,
                       const float* __restrict__ bhh)
{
    int i0 = blockIdx.x * blockDim.x + threadIdx.x;
    int stride = gridDim.x * blockDim.x;
    for (int i = i0; i < 128*128; i += stride) { int k = i >> 7, o = i & 127; g_w1t[i] = W1[o*128 + k]; }
    for (int i = i0; i < 128*32;  i += stride) { int k = i / 32, o = i % 32;  g_w2t[i] = W2[o*128 + k]; }
    for (int i = i0; i < 32*128;  i += stride) { int k = i >> 7, o = i & 127; g_w3t[i] = W3[o*32  + k]; }
    for (int i = i0; i < 19*128;  i += stride) { int o = i >> 7, k = i & 127; g_whead[i] = (o < 18) ? Wa[o*128 + k] : Wc[k]; }
    for (int i = i0; i < 19;      i += stride) g_bhead[i] = (i < 18) ? ba[i] : bc[0];
    for (int i = i0; i < 512;     i += stride) g_biasg[i] = bih[i] + bhh[i];
    for (int i = i0; i < 512*128; i += stride) {
        float w = Wih[i];
        __nv_bfloat16 hb = __float2bfloat16(w);
        g_wbhi[i] = hb;
        g_wblo[i] = __float2bfloat16(w - __bfloat162float(hb));
        float v = Whh[i];
        __nv_bfloat16 vb = __float2bfloat16(v);
        g_whhbhi[i] = vb;
        g_whhblo[i] = __float2bfloat16(v - __bfloat162float(vb));
    }
}

// -------- fused 3-layer MLP encoder: 16 rows/block, bf16 hi/lo output --------
__global__ void __launch_bounds__(256) k_enc(const float* __restrict__ x,
    const float* __restrict__ b1, const float* __restrict__ b2, const float* __restrict__ b3)
{
    __shared__ float xs [16][132];
    __shared__ float h1s[16][132];
    __shared__ float h2s[16][36];
    int tid = threadIdx.x;
    size_t row0 = (size_t)blockIdx.x * 16;
    for (int i = tid; i < 16*128; i += 256) { int r = i >> 7, k = i & 127; xs[r][k] = x[(row0 + r)*128 + k]; }
    __syncthreads();
    int tx = tid & 15, ty = tid >> 4;
    int c0 = tx * 8;
    {
        u64 acc[4];
        ulonglong2 bb0 = *(const ulonglong2*)&b1[c0];
        ulonglong2 bb1 = *(const ulonglong2*)&b1[c0 + 4];
        acc[0] = bb0.x; acc[1] = bb0.y; acc[2] = bb1.x; acc[3] = bb1.y;
        #pragma unroll 8
        for (int k = 0; k < 128; k++) {
            ulonglong2 w0 = *(const ulonglong2*)&g_w1t[k*128 + c0];
            ulonglong2 w1 = *(const ulonglong2*)&g_w1t[k*128 + c0 + 4];
            u64 A = dup2(xs[ty][k]);
            acc[0] = ffma2(A, w0.x, acc[0]); acc[1] = ffma2(A, w0.y, acc[1]);
            acc[2] = ffma2(A, w1.x, acc[2]); acc[3] = ffma2(A, w1.y, acc[3]);
        }
        #pragma unroll
        for (int cp = 0; cp < 4; cp++) {
            float lo, hi; upk(acc[cp], lo, hi);
            h1s[ty][c0 + 2*cp]     = fmaxf(lo, 0.f);
            h1s[ty][c0 + 2*cp + 1] = fmaxf(hi, 0.f);
        }
    }
    __syncthreads();
    {
        int r = tid >> 4;
        int c = (tid & 15) * 2;
        u64 acc = *(const u64*)&b2[c];
        #pragma unroll 8
        for (int k = 0; k < 128; k++) {
            u64 w = *(const u64*)&g_w2t[k*32 + c];
            u64 A = dup2(h1s[r][k]);
            acc = ffma2(A, w, acc);
        }
        float lo, hi; upk(acc, lo, hi);
        h2s[r][c] = fmaxf(lo, 0.f); h2s[r][c + 1] = fmaxf(hi, 0.f);
    }
    __syncthreads();
    {
        u64 acc[4];
        ulonglong2 bb0 = *(const ulonglong2*)&b3[c0];
        ulonglong2 bb1 = *(const ulonglong2*)&b3[c0 + 4];
        acc[0] = bb0.x; acc[1] = bb0.y; acc[2] = bb1.x; acc[3] = bb1.y;
        #pragma unroll
        for (int k = 0; k < 32; k++) {
            ulonglong2 w0 = *(const ulonglong2*)&g_w3t[k*128 + c0];
            ulonglong2 w1 = *(const ulonglong2*)&g_w3t[k*128 + c0 + 4];
            u64 A = dup2(h2s[ty][k]);
            acc[0] = ffma2(A, w0.x, acc[0]); acc[1] = ffma2(A, w0.y, acc[1]);
            acc[2] = ffma2(A, w1.x, acc[2]); acc[3] = ffma2(A, w1.y, acc[3]);
        }
        __align__(16) __nv_bfloat16 hv[8];
        __align__(16) __nv_bfloat16 lv[8];
        #pragma unroll
        for (int cp = 0; cp < 4; cp++) {
            float lo, hi; upk(acc[cp], lo, hi);
            lo = fmaxf(lo, 0.f); hi = fmaxf(hi, 0.f);
            __nv_bfloat16 h0b = __float2bfloat16(lo);
            __nv_bfloat16 h1b = __float2bfloat16(hi);
            hv[2*cp]   = h0b; hv[2*cp+1] = h1b;
            lv[2*cp]   = __float2bfloat16(lo - __bfloat162float(h0b));
            lv[2*cp+1] = __float2bfloat16(hi - __bfloat162float(h1b));
        }
        size_t off = (row0 + ty) * 128 + c0;
        *(uint4*)&g_hid_hi[off] = *(const uint4*)hv;
        *(uint4*)&g_hid_lo[off] = *(const uint4*)lv;
    }
}

// -------- xg = hid @ WihT + bias via mma.sync bf16 hi/lo split --------
#define ASTR 136
#define XG_TILE_BYTES (128 * ASTR * 2)
#define XG_DYN_SMEM (4 * XG_TILE_BYTES + 512 + 16)

__global__ void __launch_bounds__(256) k_xgmma()
{
    extern __shared__ char dyn[];
    __nv_bfloat16* smb = (__nv_bfloat16*)dyn;
    float* sbias = (float*)(dyn + 4 * XG_TILE_BYTES);
    int tid = threadIdx.x;
    int wid = tid >> 5, lane = tid & 31;
    size_t row0 = (size_t)blockIdx.x * 128;
    int col0 = blockIdx.y * 128;

    for (int i = tid; i < 128 * 16; i += 256) {
        int r = i >> 4, v = i & 15;
        size_t goff = (row0 + r) * 128 + v * 8;
        int soff = r * ASTR + v * 8;
        *(uint4*)&smb[soff]              = *(const uint4*)&g_hid_hi[goff];
        *(uint4*)&smb[128*ASTR + soff]   = *(const uint4*)&g_hid_lo[goff];
        size_t woff = (size_t)(col0 + r) * 128 + v * 8;
        *(uint4*)&smb[2*128*ASTR + soff] = *(const uint4*)&g_wbhi[woff];
        *(uint4*)&smb[3*128*ASTR + soff] = *(const uint4*)&g_wblo[woff];
    }
    if (tid < 128) sbias[tid] = g_biasg[col0 + tid];
    __syncthreads();

    uint32_t smbase = smem_to_u32(smb);
    int wm = (wid & 3) * 32;
    int wn = (wid >> 2) * 64;
    int sub = lane >> 3, rowl = lane & 7;

    float acc[2][8][4];
    #pragma unroll
    for (int mt = 0; mt < 2; mt++)
        #pragma unroll
        for (int nt = 0; nt < 8; nt++)
            #pragma unroll
            for (int q = 0; q < 4; q++) acc[mt][nt][q] = 0.f;

    const uint32_t aBase[3] = {0u, 0u, (uint32_t)XG_TILE_BYTES};
    const uint32_t bBase[3] = {2u*XG_TILE_BYTES, 3u*XG_TILE_BYTES, 2u*XG_TILE_BYTES};

    int a_row_part = (sub & 1) * 8 + rowl;
    int a_col_part = (sub >> 1) * 8;
    int b_row_part = (sub >> 1) * 8 + rowl;
    int b_col_part = (sub & 1) * 8;

    #pragma unroll
    for (int pass = 0; pass < 3; pass++) {
        uint32_t aB = smbase + aBase[pass];
        uint32_t bB = smbase + bBase[pass];
        #pragma unroll
        for (int kc = 0; kc < 8; kc++) {
            uint32_t af[2][4];
            #pragma unroll
            for (int mt = 0; mt < 2; mt++) {
                uint32_t addr = aB + ((wm + mt*16 + a_row_part) * ASTR + kc*16 + a_col_part) * 2;
                ldsm4(af[mt][0], af[mt][1], af[mt][2], af[mt][3], addr);
            }
            uint32_t bf_[8][2];
            #pragma unroll
            for (int np = 0; np < 4; np++) {
                uint32_t addr = bB + ((wn + np*16 + b_row_part) * ASTR + kc*16 + b_col_part) * 2;
                uint32_t r0, r1, r2, r3;
                ldsm4(r0, r1, r2, r3, addr);
                bf_[np*2][0] = r0; bf_[np*2][1] = r1;
                bf_[np*2+1][0] = r2; bf_[np*2+1][1] = r3;
            }
            #pragma unroll
            for (int mt = 0; mt < 2; mt++)
                #pragma unroll
                for (int nt = 0; nt < 8; nt++)
                    mma16816(acc[mt][nt], af[mt], bf_[nt]);
        }
    }

    int g = lane >> 2, tg = lane & 3;
    #pragma unroll
    for (int mt = 0; mt < 2; mt++) {
        size_t r_top = row0 + wm + mt*16 + g;
        #pragma unroll
        for (int nt = 0; nt < 8; nt++) {
            int cl = wn + nt*8 + tg*2;
            float b0 = sbias[cl], b1 = sbias[cl + 1];
            float* o0 = &g_xg[r_top * 512 + col0 + cl];
            *(float2*)o0 = make_float2(acc[mt][nt][0] + b0, acc[mt][nt][1] + b1);
            float* o1 = &g_xg[(r_top + 8) * 512 + col0 + cl];
            *(float2*)o1 = make_float2(acc[mt][nt][2] + b0, acc[mt][nt][3] + b1);
        }
    }
}

// -------- LSTM recurrence on tensor cores + fused head --------
// Per block: 8 batch elems, gates^T[512,8] = Whh[512,128] @ h^T[128,8].
// 16 warps x 32 gates (2 m-tiles). Whh_hi frags in regs, Whh_lo in smem,
// h as bf16 hi/lo rows [e][k] in smem. 3 passes: Whi*hhi + Whi*hlo + Wlo*hhi.
#define WSTR 136   // bf16 per row (128 + 8 pad); 272B, 16B-aligned stride

struct __align__(16) Rec2 {
    __nv_bfloat16 wlo[512 * WSTR];   // 139264B (also Whi staging at init)
    __nv_bfloat16 hhi[8 * WSTR];     // 2176
    __nv_bfloat16 hlo[8 * WSTR];     // 2176
    float act[512 * 12];             // 24576 (rows padded to 48B)
    float hout[2][8][128];           // 8192
    float whead[19][132];            // 10032
    float bhead[20];
    float dmask[2][8];
};

__global__ void __launch_bounds__(512, 1) k_rec(const float* __restrict__ done,
    const float* __restrict__ h0, const float* __restrict__ c0,
    float* __restrict__ out)
{
    extern __shared__ char smraw[];
    Rec2& sm = *(Rec2*)smraw;
    int j = threadIdx.x;
    int wid = j >> 5, lane = j & 31;
    int wm = wid * 32;
    int base = blockIdx.x * 8;

    // ---- stage Whh_hi into wlo area, ldmatrix to regs ----
    for (int i = j; i < 512 * 16; i += 512) {
        int r = i >> 4, v = i & 15;
        *(uint4*)&sm.wlo[r * WSTR + v * 8] = *(const uint4*)&g_whhbhi[r * 128 + v * 8];
    }
    __syncthreads();
    uint32_t wf[64];   // Whh_hi fragments: [mt][kt][4]
    {
        uint32_t abase = smem_to_u32(sm.wlo)
            + (wm + ((lane >> 3) & 1) * 8 + (lane & 7)) * (WSTR * 2)
            + ((lane >> 4) & 1) * 16;
        #pragma unroll
        for (int mt = 0; mt < 2; mt++)
            #pragma unroll
            for (int kt = 0; kt < 8; kt++)
                ldsm4(wf[(mt*8+kt)*4], wf[(mt*8+kt)*4+1], wf[(mt*8+kt)*4+2], wf[(mt*8+kt)*4+3],
                      abase + mt * 16 * (WSTR * 2) + kt * 32);
    }
    __syncthreads();
    // ---- overwrite staging with Whh_lo; load head weights; init h,c ----
    for (int i = j; i < 512 * 16; i += 512) {
        int r = i >> 4, v = i & 15;
        *(uint4*)&sm.wlo[r * WSTR + v * 8] = *(const uint4*)&g_whhblo[r * 128 + v * 8];
    }
    for (int i = j; i < 19*128; i += 512) sm.whead[i >> 7][i & 127] = g_whead[i];
    if (j < 19) sm.bhead[j] = g_bhead[j];
    if (j < 8)  sm.dmask[0][j] = 1.0f - done[base + j];

    float cst[8];
    if (j < 128) {
        #pragma unroll
        for (int e = 0; e < 8; e++) {
            int b = base + e;
            float m0 = 1.0f - done[b];
            cst[e] = c0[b*128 + j];
            float hn = h0[b*128 + j] * m0;
            __nv_bfloat16 hb = __float2bfloat16(hn);
            sm.hhi[e*WSTR + j] = hb;
            sm.hlo[e*WSTR + j] = __float2bfloat16(hn - __bfloat162float(hb));
        }
    }
    __syncthreads();

    bool isg = (wid >= 8 && wid < 12);   // tanh block: gates 256..383
    int g0 = wm + (lane >> 2);
    int e0 = (lane & 3) * 2;
    uint32_t hhibase = smem_to_u32(sm.hhi) + (lane & 7) * (WSTR*2) + ((lane >> 3) & 1) * 16;
    uint32_t hlobase = smem_to_u32(sm.hlo) + (lane & 7) * (WSTR*2) + ((lane >> 3) & 1) * 16;
    uint32_t wlobase = smem_to_u32(sm.wlo)
        + (wm + ((lane >> 3) & 1) * 8 + (lane & 7)) * (WSTR*2)
        + ((lane >> 4) & 1) * 16;

    for (int t = 0; t < TT; t++) {
        // ---- phase A: gates^T = Whh @ h^T (tensor cores) ----
        float xv[8];
        {
            const float* xrow = g_xg + ((size_t)t * BB + base) * 512;
            #pragma unroll
            for (int mt = 0; mt < 2; mt++) {
                int g = g0 + mt * 16;
                xv[mt*4+0] = xrow[(size_t)(e0    ) * 512 + g];
                xv[mt*4+1] = xrow[(size_t)(e0 + 1) * 512 + g];
                xv[mt*4+2] = xrow[(size_t)(e0    ) * 512 + g + 8];
                xv[mt*4+3] = xrow[(size_t)(e0 + 1) * 512 + g + 8];
            }
            int tn = (t + 1 < TT) ? (t + 1) : t;
            if (j < 8) sm.dmask[(t + 1) & 1][j] = 1.0f - done[(size_t)tn * BB + base + j];
        }
        float acc[2][4] = {{0.f,0.f,0.f,0.f},{0.f,0.f,0.f,0.f}};
        #pragma unroll
        for (int kt = 0; kt < 8; kt++) {
            uint32_t bh[2], bl[2];
            ldsm2(bh[0], bh[1], hhibase + kt * 32);
            ldsm2(bl[0], bl[1], hlobase + kt * 32);
            #pragma unroll
            for (int mt = 0; mt < 2; mt++) {
                uint32_t al[4];
                ldsm4(al[0], al[1], al[2], al[3], wlobase + mt * 16 * (WSTR*2) + kt * 32);
                mma16816(acc[mt], &wf[(mt*8+kt)*4], bh);
                mma16816(acc[mt], &wf[(mt*8+kt)*4], bl);
                mma16816(acc[mt], al, bh);
            }
        }
        // activations -> act smem (rows = gate, cols = elem)
        #pragma unroll
        for (int mt = 0; mt < 2; mt++) {
            int g = g0 + mt * 16;
            float v0 = acc[mt][0] + xv[mt*4+0];
            float v1 = acc[mt][1] + xv[mt*4+1];
            float v2 = acc[mt][2] + xv[mt*4+2];
            float v3 = acc[mt][3] + xv[mt*4+3];
            if (isg) { v0 = tanh_f(v0); v1 = tanh_f(v1); v2 = tanh_f(v2); v3 = tanh_f(v3); }
            else     { v0 = sig_f(v0);  v1 = sig_f(v1);  v2 = sig_f(v2);  v3 = sig_f(v3);  }
            *(float2*)&sm.act[g * 12 + e0]       = make_float2(v0, v1);
            *(float2*)&sm.act[(g + 8) * 12 + e0] = make_float2(v2, v3);
        }
        __syncthreads();

        // ---- phase B: cell update (warps 0-3) | head t-1 (warps 4-8) ----
        if (j < 128) {
            float ivv[8], fvv[8], gvv[8], ovv[8];
            *(float4*)&ivv[0] = *(const float4*)&sm.act[j * 12];
            *(float4*)&ivv[4] = *(const float4*)&sm.act[j * 12 + 4];
            *(float4*)&fvv[0] = *(const float4*)&sm.act[(j + 128) * 12];
            *(float4*)&fvv[4] = *(const float4*)&sm.act[(j + 128) * 12 + 4];
            *(float4*)&gvv[0] = *(const float4*)&sm.act[(j + 256) * 12];
            *(float4*)&gvv[4] = *(const float4*)&sm.act[(j + 256) * 12 + 4];
            *(float4*)&ovv[0] = *(const float4*)&sm.act[(j + 384) * 12];
            *(float4*)&ovv[4] = *(const float4*)&sm.act[(j + 384) * 12 + 4];
            const float* mrow = sm.dmask[t & 1];
            const float* nrow = sm.dmask[(t + 1) & 1];
            float* ho = &sm.hout[t & 1][0][0];
            #pragma unroll
            for (int e = 0; e < 8; e++) {
                float cc = fvv[e] * (cst[e] * mrow[e]) + ivv[e] * gvv[e];
                cst[e] = cc;
                float h = ovv[e] * tanh_f(cc);
                ho[e * 128 + j] = h;
                float hn = h * nrow[e];
                __nv_bfloat16 hb = __float2bfloat16(hn);
                sm.hhi[e * WSTR + j] = hb;
                sm.hlo[e * WSTR + j] = __float2bfloat16(hn - __bfloat162float(hb));
            }
        } else if (t > 0) {
            int j2 = j - 128;
            if (j2 < 152) {
                int e = j2 / 19, o = j2 - e * 19;
                const float* hv = sm.hout[(t - 1) & 1][e];
                const float* wv = sm.whead[o];
                float a = sm.bhead[o];
                #pragma unroll
                for (int k = 0; k < 128; k += 4) {
                    float4 h4 = *(const float4*)&hv[k];
                    float4 w4 = *(const float4*)&wv[k];
                    a += h4.x*w4.x + h4.y*w4.y + h4.z*w4.z + h4.w*w4.w;
                }
                out[((size_t)(t - 1) * BB + base + e) * 19 + o] = a;
            }
        }
        __syncthreads();
    }

    // ---- epilogue: head for t = TT-1 ----
    if (j < 152) {
        int e = j / 19, o = j - e * 19;
        const float* hv = sm.hout[(TT - 1) & 1][e];
        const float* wv = sm.whead[o];
        float a = sm.bhead[o];
        #pragma unroll
        for (int k = 0; k < 128; k += 4) {
            float4 h4 = *(const float4*)&hv[k];
            float4 w4 = *(const float4*)&wv[k];
            a += h4.x*w4.x + h4.y*w4.y + h4.z*w4.z + h4.w*w4.w;
        }
        out[((size_t)(TT - 1) * BB + base + e) * 19 + o] = a;
    }
}

extern "C" void kernel_launch(void* const* d_in, const int* in_sizes, int n_in,
                              void* d_out, int out_size)
{
    const float* x    = (const float*)d_in[0];
    const float* done = (const float*)d_in[1];
    const float* h0   = (const float*)d_in[2];
    const float* c0   = (const float*)d_in[3];
    const float* W1   = (const float*)d_in[4];
    const float* b1   = (const float*)d_in[5];
    const float* W2   = (const float*)d_in[6];
    const float* b2   = (const float*)d_in[7];
    const float* W3   = (const float*)d_in[8];
    const float* b3   = (const float*)d_in[9];
    const float* Wih  = (const float*)d_in[10];
    const float* Whh  = (const float*)d_in[11];
    const float* bih  = (const float*)d_in[12];
    const float* bhh  = (const float*)d_in[13];
    const float* Wa   = (const float*)d_in[14];
    const float* ba   = (const float*)d_in[15];
    const float* Wc   = (const float*)d_in[16];
    const float* bc   = (const float*)d_in[17];

    int rec_smem = (int)sizeof(Rec2);
    cudaFuncSetAttribute(k_rec, cudaFuncAttributeMaxDynamicSharedMemorySize, rec_smem);
    cudaFuncSetAttribute(k_xgmma, cudaFuncAttributeMaxDynamicSharedMemorySize, XG_DYN_SMEM);

    k_prep<<<256, 256>>>(W1, W2, W3, Wih, Whh, Wa, ba, Wc, bc, bih, bhh);
    k_enc<<<NROW/16, 256>>>(x, b1, b2, b3);
    dim3 gmm(NROW/128, 4);
    k_xgmma<<<gmm, 256, XG_DYN_SMEM>>>();
    k_rec<<<128, 512, rec_smem>>>(done, h0, c0, (float*)d_out);
}

// round 12
// speedup vs baseline: 2.4432x; 1.3191x over previous
#include <cuda_runtime.h>
#include <cuda_bf16.h>
#include <cstdint>

// Problem dims (fixed by the dataset)
#define TT 256
#define BB 1024
#define NROW (TT*BB)   // 262144

typedef unsigned long long u64;

// -------- device scratch (no allocations allowed) --------
__device__ __nv_bfloat16 g_hid_hi[(size_t)NROW * 128];  // encoder out, bf16 hi   64MB
__device__ __nv_bfloat16 g_hid_lo[(size_t)NROW * 128];  // encoder out, bf16 lo   64MB
__device__ float g_xg [(size_t)NROW * 512];             // x@Wih.T + bias        537MB
__device__ float g_w1t [128 * 128];                     // W1 transposed [k][o]
__device__ float g_w2t [128 * 32];
__device__ float g_w3t [32 * 128];
__device__ __align__(16) float g_whead[19 * 128];       // [Wa;Wc]
__device__ float g_bhead[19];
__device__ float g_biasg[512];                          // bih + bhh
__device__ __nv_bfloat16 g_wbhi[512 * 128];             // Wih bf16 hi  [gate][k]
__device__ __nv_bfloat16 g_wblo[512 * 128];             // Wih bf16 lo  [gate][k]
__device__ __nv_bfloat16 g_whhbhi[512 * 128];           // Whh bf16 hi  [gate][k]
__device__ __nv_bfloat16 g_whhblo[512 * 128];           // Whh bf16 lo  [gate][k]

// -------- PTX helpers --------
__device__ __forceinline__ uint32_t smem_to_u32(const void* p) {
    uint32_t a;
    asm("{ .reg .u64 t; cvta.to.shared.u64 t, %1; cvt.u32.u64 %0, t; }" : "=r"(a) : "l"(p));
    return a;
}
__device__ __forceinline__ void ldsm4(uint32_t& r0, uint32_t& r1, uint32_t& r2, uint32_t& r3,
                                      uint32_t addr) {
    asm volatile("ldmatrix.sync.aligned.m8n8.x4.shared.b16 {%0,%1,%2,%3}, [%4];"
                 : "=r"(r0), "=r"(r1), "=r"(r2), "=r"(r3) : "r"(addr));
}
__device__ __forceinline__ void ldsm2(uint32_t& r0, uint32_t& r1, uint32_t addr) {
    asm volatile("ldmatrix.sync.aligned.m8n8.x2.shared.b16 {%0,%1}, [%2];"
                 : "=r"(r0), "=r"(r1) : "r"(addr));
}
__device__ __forceinline__ void mma16816(float* d, const uint32_t* a, const uint32_t* b) {
    asm volatile(
        "mma.sync.aligned.m16n8k16.row.col.f32.bf16.bf16.f32 "
        "{%0,%1,%2,%3},{%4,%5,%6,%7},{%8,%9},{%0,%1,%2,%3};"
        : "+f"(d[0]), "+f"(d[1]), "+f"(d[2]), "+f"(d[3])
        : "r"(a[0]), "r"(a[1]), "r"(a[2]), "r"(a[3]), "r"(b[0]), "r"(b[1]));
}

// -------- packed f32x2 helpers --------
__device__ __forceinline__ u64 pk2(float lo, float hi) {
    u64 r; asm("mov.b64 %0,{%1,%2};" : "=l"(r) : "f"(lo), "f"(hi)); return r;
}
__device__ __forceinline__ u64 dup2(float v) { return pk2(v, v); }
__device__ __forceinline__ void upk(u64 p, float& lo, float& hi) {
    asm("mov.b64 {%0,%1},%2;" : "=f"(lo), "=f"(hi) : "l"(p));
}
__device__ __forceinline__ u64 ffma2(u64 a, u64 b, u64 c) {
    u64 d; asm("fma.rn.f32x2 %0,%1,%2,%3;" : "=l"(d) : "l"(a), "l"(b), "l"(c)); return d;
}
__device__ __forceinline__ float sig_f(float v) {
    return __fdividef(1.f, 1.f + __expf(-v));
}
__device__ __forceinline__ float tanh_f(float v) {
    return 2.f * sig_f(2.f * v) - 1.f;
}

// -------- prep --------
__global__ void k_prep(const float* __restrict__ W1, const float* __restrict__ W2,
                       const float* __restrict__ W3, const float* __restrict__ Wih,
                       const float* __restrict__ Whh, const float* __restrict__ Wa,
                       const float* __restrict__ ba, const float* __restrict__ Wc,
                       const float* __restrict__ bc, const float* __restrict__ bih,
                       const float* __restrict__ bhh)
{
    int i0 = blockIdx.x * blockDim.x + threadIdx.x;
    int stride = gridDim.x * blockDim.x;
    for (int i = i0; i < 128*128; i += stride) { int k = i >> 7, o = i & 127; g_w1t[i] = W1[o*128 + k]; }
    for (int i = i0; i < 128*32;  i += stride) { int k = i / 32, o = i % 32;  g_w2t[i] = W2[o*128 + k]; }
    for (int i = i0; i < 32*128;  i += stride) { int k = i >> 7, o = i & 127; g_w3t[i] = W3[o*32  + k]; }
    for (int i = i0; i < 19*128;  i += stride) { int o = i >> 7, k = i & 127; g_whead[i] = (o < 18) ? Wa[o*128 + k] : Wc[k]; }
    for (int i = i0; i < 19;      i += stride) g_bhead[i] = (i < 18) ? ba[i] : bc[0];
    for (int i = i0; i < 512;     i += stride) g_biasg[i] = bih[i] + bhh[i];
    for (int i = i0; i < 512*128; i += stride) {
        float w = Wih[i];
        __nv_bfloat16 hb = __float2bfloat16(w);
        g_wbhi[i] = hb;
        g_wblo[i] = __float2bfloat16(w - __bfloat162float(hb));
        float v = Whh[i];
        __nv_bfloat16 vb = __float2bfloat16(v);
        g_whhbhi[i] = vb;
        g_whhblo[i] = __float2bfloat16(v - __bfloat162float(vb));
    }
}

// -------- fused 3-layer MLP encoder: 64 rows/block, 4 rows/thread --------
#define ENC_SMEM ((64*132 + 64*132 + 64*36) * 4)

__global__ void __launch_bounds__(256) k_enc(const float* __restrict__ x,
    const float* __restrict__ b1, const float* __restrict__ b2, const float* __restrict__ b3)
{
    extern __shared__ float es[];
    float* xs  = es;                  // [64][132]
    float* h1s = es + 64*132;         // [64][132]
    float* h2s = h1s + 64*132;        // [64][36]
    int tid = threadIdx.x;
    size_t row0 = (size_t)blockIdx.x * 64;
    for (int i = tid; i < 64*128; i += 256) { int r = i >> 7, k = i & 127; xs[r*132 + k] = x[(row0 + r)*128 + k]; }
    __syncthreads();
    int tx = tid & 15, ty = tid >> 4;
    int c0 = tx * 8, r0 = ty * 4;
    // stage 1: relu(x @ W1T + b1) -> h1s (4 rows per thread)
    {
        u64 acc[4][4];
        ulonglong2 bb0 = *(const ulonglong2*)&b1[c0];
        ulonglong2 bb1 = *(const ulonglong2*)&b1[c0 + 4];
        #pragma unroll
        for (int i = 0; i < 4; i++) { acc[i][0] = bb0.x; acc[i][1] = bb0.y; acc[i][2] = bb1.x; acc[i][3] = bb1.y; }
        #pragma unroll 4
        for (int k = 0; k < 128; k++) {
            ulonglong2 w0 = *(const ulonglong2*)&g_w1t[k*128 + c0];
            ulonglong2 w1 = *(const ulonglong2*)&g_w1t[k*128 + c0 + 4];
            #pragma unroll
            for (int i = 0; i < 4; i++) {
                u64 A = dup2(xs[(r0 + i)*132 + k]);
                acc[i][0] = ffma2(A, w0.x, acc[i][0]); acc[i][1] = ffma2(A, w0.y, acc[i][1]);
                acc[i][2] = ffma2(A, w1.x, acc[i][2]); acc[i][3] = ffma2(A, w1.y, acc[i][3]);
            }
        }
        #pragma unroll
        for (int i = 0; i < 4; i++)
            #pragma unroll
            for (int cp = 0; cp < 4; cp++) {
                float lo, hi; upk(acc[i][cp], lo, hi);
                h1s[(r0 + i)*132 + c0 + 2*cp]     = fmaxf(lo, 0.f);
                h1s[(r0 + i)*132 + c0 + 2*cp + 1] = fmaxf(hi, 0.f);
            }
    }
    __syncthreads();
    // stage 2: relu(h1 @ W2T + b2) -> h2s
    {
        int c = tx * 2;
        u64 acc[4];
        u64 bb = *(const u64*)&b2[c];
        #pragma unroll
        for (int i = 0; i < 4; i++) acc[i] = bb;
        #pragma unroll 4
        for (int k = 0; k < 128; k++) {
            u64 w = *(const u64*)&g_w2t[k*32 + c];
            #pragma unroll
            for (int i = 0; i < 4; i++) {
                u64 A = dup2(h1s[(r0 + i)*132 + k]);
                acc[i] = ffma2(A, w, acc[i]);
            }
        }
        #pragma unroll
        for (int i = 0; i < 4; i++) {
            float lo, hi; upk(acc[i], lo, hi);
            h2s[(r0 + i)*36 + c] = fmaxf(lo, 0.f);
            h2s[(r0 + i)*36 + c + 1] = fmaxf(hi, 0.f);
        }
    }
    __syncthreads();
    // stage 3: relu(h2 @ W3T + b3) -> bf16 hi/lo
    {
        u64 acc[4][4];
        ulonglong2 bb0 = *(const ulonglong2*)&b3[c0];
        ulonglong2 bb1 = *(const ulonglong2*)&b3[c0 + 4];
        #pragma unroll
        for (int i = 0; i < 4; i++) { acc[i][0] = bb0.x; acc[i][1] = bb0.y; acc[i][2] = bb1.x; acc[i][3] = bb1.y; }
        #pragma unroll
        for (int k = 0; k < 32; k++) {
            ulonglong2 w0 = *(const ulonglong2*)&g_w3t[k*128 + c0];
            ulonglong2 w1 = *(const ulonglong2*)&g_w3t[k*128 + c0 + 4];
            #pragma unroll
            for (int i = 0; i < 4; i++) {
                u64 A = dup2(h2s[(r0 + i)*36 + k]);
                acc[i][0] = ffma2(A, w0.x, acc[i][0]); acc[i][1] = ffma2(A, w0.y, acc[i][1]);
                acc[i][2] = ffma2(A, w1.x, acc[i][2]); acc[i][3] = ffma2(A, w1.y, acc[i][3]);
            }
        }
        #pragma unroll
        for (int i = 0; i < 4; i++) {
            __align__(16) __nv_bfloat16 hv[8];
            __align__(16) __nv_bfloat16 lv[8];
            #pragma unroll
            for (int cp = 0; cp < 4; cp++) {
                float lo, hi; upk(acc[i][cp], lo, hi);
                lo = fmaxf(lo, 0.f); hi = fmaxf(hi, 0.f);
                __nv_bfloat16 h0b = __float2bfloat16(lo);
                __nv_bfloat16 h1b = __float2bfloat16(hi);
                hv[2*cp]   = h0b; hv[2*cp+1] = h1b;
                lv[2*cp]   = __float2bfloat16(lo - __bfloat162float(h0b));
                lv[2*cp+1] = __float2bfloat16(hi - __bfloat162float(h1b));
            }
            size_t off = (row0 + r0 + i) * 128 + c0;
            *(uint4*)&g_hid_hi[off] = *(const uint4*)hv;
            *(uint4*)&g_hid_lo[off] = *(const uint4*)lv;
        }
    }
}

// -------- xg = hid @ WihT + bias via mma.sync bf16 hi/lo split --------
#define ASTR 136
#define XG_TILE_BYTES (128 * ASTR * 2)
#define XG_DYN_SMEM (4 * XG_TILE_BYTES + 512 + 16)

__global__ void __launch_bounds__(256) k_xgmma()
{
    extern __shared__ char dyn[];
    __nv_bfloat16* smb = (__nv_bfloat16*)dyn;
    float* sbias = (float*)(dyn + 4 * XG_TILE_BYTES);
    int tid = threadIdx.x;
    int wid = tid >> 5, lane = tid & 31;
    size_t row0 = (size_t)blockIdx.x * 128;
    int col0 = blockIdx.y * 128;

    for (int i = tid; i < 128 * 16; i += 256) {
        int r = i >> 4, v = i & 15;
        size_t goff = (row0 + r) * 128 + v * 8;
        int soff = r * ASTR + v * 8;
        *(uint4*)&smb[soff]              = *(const uint4*)&g_hid_hi[goff];
        *(uint4*)&smb[128*ASTR + soff]   = *(const uint4*)&g_hid_lo[goff];
        size_t woff = (size_t)(col0 + r) * 128 + v * 8;
        *(uint4*)&smb[2*128*ASTR + soff] = *(const uint4*)&g_wbhi[woff];
        *(uint4*)&smb[3*128*ASTR + soff] = *(const uint4*)&g_wblo[woff];
    }
    if (tid < 128) sbias[tid] = g_biasg[col0 + tid];
    __syncthreads();

    uint32_t smbase = smem_to_u32(smb);
    int wm = (wid & 3) * 32;
    int wn = (wid >> 2) * 64;
    int sub = lane >> 3, rowl = lane & 7;

    float acc[2][8][4];
    #pragma unroll
    for (int mt = 0; mt < 2; mt++)
        #pragma unroll
        for (int nt = 0; nt < 8; nt++)
            #pragma unroll
            for (int q = 0; q < 4; q++) acc[mt][nt][q] = 0.f;

    const uint32_t aBase[3] = {0u, 0u, (uint32_t)XG_TILE_BYTES};
    const uint32_t bBase[3] = {2u*XG_TILE_BYTES, 3u*XG_TILE_BYTES, 2u*XG_TILE_BYTES};

    int a_row_part = (sub & 1) * 8 + rowl;
    int a_col_part = (sub >> 1) * 8;
    int b_row_part = (sub >> 1) * 8 + rowl;
    int b_col_part = (sub & 1) * 8;

    #pragma unroll
    for (int pass = 0; pass < 3; pass++) {
        uint32_t aB = smbase + aBase[pass];
        uint32_t bB = smbase + bBase[pass];
        #pragma unroll
        for (int kc = 0; kc < 8; kc++) {
            uint32_t af[2][4];
            #pragma unroll
            for (int mt = 0; mt < 2; mt++) {
                uint32_t addr = aB + ((wm + mt*16 + a_row_part) * ASTR + kc*16 + a_col_part) * 2;
                ldsm4(af[mt][0], af[mt][1], af[mt][2], af[mt][3], addr);
            }
            uint32_t bf_[8][2];
            #pragma unroll
            for (int np = 0; np < 4; np++) {
                uint32_t addr = bB + ((wn + np*16 + b_row_part) * ASTR + kc*16 + b_col_part) * 2;
                uint32_t r0, r1, r2, r3;
                ldsm4(r0, r1, r2, r3, addr);
                bf_[np*2][0] = r0; bf_[np*2][1] = r1;
                bf_[np*2+1][0] = r2; bf_[np*2+1][1] = r3;
            }
            #pragma unroll
            for (int mt = 0; mt < 2; mt++)
                #pragma unroll
                for (int nt = 0; nt < 8; nt++)
                    mma16816(acc[mt][nt], af[mt], bf_[nt]);
        }
    }

    int g = lane >> 2, tg = lane & 3;
    #pragma unroll
    for (int mt = 0; mt < 2; mt++) {
        size_t r_top = row0 + wm + mt*16 + g;
        #pragma unroll
        for (int nt = 0; nt < 8; nt++) {
            int cl = wn + nt*8 + tg*2;
            float b0 = sbias[cl], b1 = sbias[cl + 1];
            float* o0 = &g_xg[r_top * 512 + col0 + cl];
            *(float2*)o0 = make_float2(acc[mt][nt][0] + b0, acc[mt][nt][1] + b1);
            float* o1 = &g_xg[(r_top + 8) * 512 + col0 + cl];
            *(float2*)o1 = make_float2(acc[mt][nt][2] + b0, acc[mt][nt][3] + b1);
        }
    }
}

// -------- LSTM recurrence on tensor cores: single sync/step --------
// Warp w owns cells [8w, 8w+8). A-fragments built from per-lane ldmatrix row
// addressing: m-tile0 atoms = (i-rows, f-rows), m-tile1 = (g-rows, o-rows) of
// those 8 cells -> each lane's accumulators hold i,f,g,o of ONE cell for 2
// elems -> warp-local cell update, no act smem, 1 syncthreads/step.
// Whh_hi: kt 0-5 in regs (48), kt 6-7 in smem. Whh_lo: smem. h: bf16 hi/lo
// double-buffered. xg + done prefetched one step ahead (reg double buffer).
// NOTE: A-operand (.x4) col-select uses lane bit 4; B-operand (.x2) uses
// lane bit 3 (addresses come from lanes 0-15 only) — distinct offsets!
#define WSTR 136          // h row stride (bf16): 272B = 16*17, uint4-safe
#define W2STR 40          // whi tail row stride (bf16): 80B = 16*5, uint4-safe

struct __align__(16) Rec3 {
    __nv_bfloat16 wlo[512 * WSTR];     // 139264B (staging for hi at init, then lo)
    __nv_bfloat16 whi2[512 * W2STR];   // 40960B  (Whh_hi k 96..127)
    __nv_bfloat16 hhi[2][8 * WSTR];    // 4352B
    __nv_bfloat16 hlo[2][8 * WSTR];    // 4352B
    float hout[2][8][128];             // 8192B   (unmasked h for head)
};

__global__ void __launch_bounds__(512, 1) k_rec(const float* __restrict__ done,
    const float* __restrict__ h0, const float* __restrict__ c0,
    float* __restrict__ out)
{
    extern __shared__ char smraw[];
    Rec3& sm = *(Rec3*)smraw;
    int j = threadIdx.x;
    int wid = j >> 5, lane = j & 31;
    int base = blockIdx.x * 8;

    // ---- fill whi2 (k 96..127) directly from global ----
    for (int i = j; i < 512 * 4; i += 512) {
        int r = i >> 2, v = i & 3;
        *(uint4*)&sm.whi2[r * W2STR + v * 8] = *(const uint4*)&g_whhbhi[r * 128 + 96 + v * 8];
    }
    // ---- stage Whh_hi into wlo area ----
    for (int i = j; i < 512 * 16; i += 512) {
        int r = i >> 4, v = i & 15;
        *(uint4*)&sm.wlo[r * WSTR + v * 8] = *(const uint4*)&g_whhbhi[r * 128 + v * 8];
    }
    __syncthreads();

    // per-lane A row: cells 8w..8w+7; atom pair (i,f) for mt0, (g,o) for mt1
    int rowA = 8 * wid + (lane & 7) + ((lane >> 3) & 1) * 128;   // + mt*256
    int koff16 = ((lane >> 4) & 1) * 16;                          // A-op col sel (bit 4)
    int hoff16 = ((lane >> 3) & 1) * 16;                          // B-op col sel (bit 3)
    uint32_t wlo_u = smem_to_u32(sm.wlo);
    uint32_t wf[48];   // hi frags kt 0..5: [mt][kt][4]
    #pragma unroll
    for (int mt = 0; mt < 2; mt++) {
        uint32_t ab = wlo_u + (rowA + mt * 256) * (WSTR * 2) + koff16;
        #pragma unroll
        for (int kt = 0; kt < 6; kt++) {
            int o = (mt * 6 + kt) * 4;
            ldsm4(wf[o], wf[o+1], wf[o+2], wf[o+3], ab + kt * 32);
        }
    }
    __syncthreads();
    // ---- overwrite staging with Whh_lo ----
    for (int i = j; i < 512 * 16; i += 512) {
        int r = i >> 4, v = i & 15;
        *(uint4*)&sm.wlo[r * WSTR + v * 8] = *(const uint4*)&g_whhblo[r * 128 + v * 8];
    }

    // ---- per-lane state: cell cc, elems e0,e0+1 ----
    int cc = 8 * wid + (lane >> 2);
    int e0 = (lane & 3) * 2;
    float c2a = c0[(base + e0) * 128 + cc];
    float c2b = c0[(base + e0 + 1) * 128 + cc];
    float dm0 = 1.0f - done[base + e0];
    float dm1 = 1.0f - done[base + e0 + 1];

    // init h (pre-masked) into buffer 0 (threads 0-127: cell j, all elems)
    if (j < 128) {
        #pragma unroll
        for (int e = 0; e < 8; e++) {
            int b = base + e;
            float hn = h0[b*128 + j] * (1.0f - done[b]);
            __nv_bfloat16 hb = __float2bfloat16(hn);
            sm.hhi[0][e*WSTR + j] = hb;
            sm.hlo[0][e*WSTR + j] = __float2bfloat16(hn - __bfloat162float(hb));
        }
    }
    // xv prefetch for t=0
    float xva[8], xvb[8];
    {
        const float* xr = g_xg + (size_t)base * 512;
        #pragma unroll
        for (int q = 0; q < 4; q++) {
            int gp = cc + q * 128;
            xva[2*q]   = xr[(size_t)e0 * 512 + gp];
            xva[2*q+1] = xr[(size_t)(e0+1) * 512 + gp];
        }
    }
    __syncthreads();

    uint32_t hhi_u = smem_to_u32(sm.hhi) + (lane & 7) * (WSTR*2) + hoff16;
    uint32_t hlo_u = smem_to_u32(sm.hlo) + (lane & 7) * (WSTR*2) + hoff16;
    uint32_t whi2_u = smem_to_u32(sm.whi2);
    const int hbufB = 8 * WSTR * 2;
    // head work split: warps 0-7 -> 10 outputs, 8-15 -> 9
    int nout  = (wid < 8) ? 10 : 9;
    int obase = (wid < 8) ? wid * 10 : 80 + (wid - 8) * 9;

    for (int t = 0; t < TT; t++) {
        int cur = t & 1, nxt = cur ^ 1;
        // -- prefetch xg + done for t+1 (consumed next step) --
        float dn0, dn1;
        {
            int tn = (t + 1 < TT) ? (t + 1) : t;
            const float* xr = g_xg + ((size_t)tn * BB + base) * 512;
            #pragma unroll
            for (int q = 0; q < 4; q++) {
                int gp = cc + q * 128;
                xvb[2*q]   = xr[(size_t)e0 * 512 + gp];
                xvb[2*q+1] = xr[(size_t)(e0+1) * 512 + gp];
            }
            dn0 = 1.0f - done[(size_t)tn * BB + base + e0];
            dn1 = 1.0f - done[(size_t)tn * BB + base + e0 + 1];
        }
        // -- head for t-1 (warp-distributed, overlaps tensor work) --
        if (t > 0) {
            const float* hob = &sm.hout[(t - 1) & 1][0][0];
            for (int d = 0; d < nout; d++) {
                int oi = obase + d;
                int e = oi / 19, o = oi - e * 19;
                float4 h4 = *(const float4*)&hob[e * 128 + lane * 4];
                float4 w4 = *(const float4*)&g_whead[o * 128 + lane * 4];
                float s = h4.x*w4.x + h4.y*w4.y + h4.z*w4.z + h4.w*w4.w;
                s += __shfl_xor_sync(0xffffffffu, s, 16);
                s += __shfl_xor_sync(0xffffffffu, s, 8);
                s += __shfl_xor_sync(0xffffffffu, s, 4);
                s += __shfl_xor_sync(0xffffffffu, s, 2);
                s += __shfl_xor_sync(0xffffffffu, s, 1);
                if (lane == 0)
                    out[((size_t)(t - 1) * BB + base + e) * 19 + o] = s + g_bhead[o];
            }
        }
        // -- MMA: gates^T = Whh @ h^T, 3-pass hi/lo --
        float acc[2][4] = {{0.f,0.f,0.f,0.f},{0.f,0.f,0.f,0.f}};
        uint32_t hb_u = hhi_u + cur * hbufB;
        uint32_t hl_u = hlo_u + cur * hbufB;
        #pragma unroll
        for (int kt = 0; kt < 8; kt++) {
            uint32_t bh[2], bl[2];
            ldsm2(bh[0], bh[1], hb_u + kt * 32);
            ldsm2(bl[0], bl[1], hl_u + kt * 32);
            #pragma unroll
            for (int mt = 0; mt < 2; mt++) {
                uint32_t al[4];
                ldsm4(al[0], al[1], al[2], al[3],
                      wlo_u + (rowA + mt * 256) * (WSTR*2) + koff16 + kt * 32);
                if (kt < 6) {
                    const uint32_t* ah = &wf[(mt * 6 + kt) * 4];
                    mma16816(acc[mt], ah, bh);
                    mma16816(acc[mt], ah, bl);
                } else {
                    uint32_t ah[4];
                    ldsm4(ah[0], ah[1], ah[2], ah[3],
                          whi2_u + (rowA + mt * 256) * (W2STR*2) + koff16 + (kt - 6) * 32);
                    mma16816(acc[mt], ah, bh);
                    mma16816(acc[mt], ah, bl);
                }
                mma16816(acc[mt], al, bh);
            }
        }
        // -- gates + activations: acc0 = (i,f) sigmoid; acc1 = (g tanh, o sigmoid) --
        float iv0 = sig_f(acc[0][0] + xva[0]), iv1 = sig_f(acc[0][1] + xva[1]);
        float fv0 = sig_f(acc[0][2] + xva[2]), fv1 = sig_f(acc[0][3] + xva[3]);
        float gv0 = tanh_f(acc[1][0] + xva[4]), gv1 = tanh_f(acc[1][1] + xva[5]);
        float ov0 = sig_f(acc[1][2] + xva[6]), ov1 = sig_f(acc[1][3] + xva[7]);
        // -- warp-local cell update --
        c2a = fv0 * (c2a * dm0) + iv0 * gv0;
        c2b = fv1 * (c2b * dm1) + iv1 * gv1;
        float ha = ov0 * tanh_f(c2a);
        float hb = ov1 * tanh_f(c2b);
        sm.hout[cur][e0][cc]     = ha;
        sm.hout[cur][e0 + 1][cc] = hb;
        float hna = ha * dn0, hnb = hb * dn1;
        __nv_bfloat16 hba = __float2bfloat16(hna);
        __nv_bfloat16 hbb = __float2bfloat16(hnb);
        sm.hhi[nxt][e0*WSTR + cc]     = hba;
        sm.hhi[nxt][(e0+1)*WSTR + cc] = hbb;
        sm.hlo[nxt][e0*WSTR + cc]     = __float2bfloat16(hna - __bfloat162float(hba));
        sm.hlo[nxt][(e0+1)*WSTR + cc] = __float2bfloat16(hnb - __bfloat162float(hbb));
        dm0 = dn0; dm1 = dn1;
        #pragma unroll
        for (int q = 0; q < 8; q++) xva[q] = xvb[q];
        __syncthreads();
    }

    // ---- epilogue: head for t = TT-1 ----
    {
        const float* hob = &sm.hout[(TT - 1) & 1][0][0];
        for (int d = 0; d < nout; d++) {
            int oi = obase + d;
            int e = oi / 19, o = oi - e * 19;
            float4 h4 = *(const float4*)&hob[e * 128 + lane * 4];
            float4 w4 = *(const float4*)&g_whead[o * 128 + lane * 4];
            float s = h4.x*w4.x + h4.y*w4.y + h4.z*w4.z + h4.w*w4.w;
            s += __shfl_xor_sync(0xffffffffu, s, 16);
            s += __shfl_xor_sync(0xffffffffu, s, 8);
            s += __shfl_xor_sync(0xffffffffu, s, 4);
            s += __shfl_xor_sync(0xffffffffu, s, 2);
            s += __shfl_xor_sync(0xffffffffu, s, 1);
            if (lane == 0)
                out[((size_t)(TT - 1) * BB + base + e) * 19 + o] = s + g_bhead[o];
        }
    }
}

extern "C" void kernel_launch(void* const* d_in, const int* in_sizes, int n_in,
                              void* d_out, int out_size)
{
    const float* x    = (const float*)d_in[0];
    const float* done = (const float*)d_in[1];
    const float* h0   = (const float*)d_in[2];
    const float* c0   = (const float*)d_in[3];
    const float* W1   = (const float*)d_in[4];
    const float* b1   = (const float*)d_in[5];
    const float* W2   = (const float*)d_in[6];
    const float* b2   = (const float*)d_in[7];
    const float* W3   = (const float*)d_in[8];
    const float* b3   = (const float*)d_in[9];
    const float* Wih  = (const float*)d_in[10];
    const float* Whh  = (const float*)d_in[11];
    const float* bih  = (const float*)d_in[12];
    const float* bhh  = (const float*)d_in[13];
    const float* Wa   = (const float*)d_in[14];
    const float* ba   = (const float*)d_in[15];
    const float* Wc   = (const float*)d_in[16];
    const float* bc   = (const float*)d_in[17];

    int rec_smem = (int)sizeof(Rec3);
    cudaFuncSetAttribute(k_rec, cudaFuncAttributeMaxDynamicSharedMemorySize, rec_smem);
    cudaFuncSetAttribute(k_xgmma, cudaFuncAttributeMaxDynamicSharedMemorySize, XG_DYN_SMEM);
    cudaFuncSetAttribute(k_enc, cudaFuncAttributeMaxDynamicSharedMemorySize, ENC_SMEM);

    k_prep<<<256, 256>>>(W1, W2, W3, Wih, Whh, Wa, ba, Wc, bc, bih, bhh);
    k_enc<<<NROW/64, 256, ENC_SMEM>>>(x, b1, b2, b3);
    dim3 gmm(NROW/128, 4);
    k_xgmma<<<gmm, 256, XG_DYN_SMEM>>>();
    k_rec<<<128, 512, rec_smem>>>(done, h0, c0, (float*)d_out);
}